// round 1
// baseline (speedup 1.0000x reference)
#include <cuda_runtime.h>
#include <cuda_bf16.h>
#include <cstdint>

// Problem dims
#define BATCH 8
#define SEQ   2048
#define EMB   1024
#define HEAD  128
#define MROWS (BATCH * SEQ)   // 16384

// Scratch for projected Q, K, V (fp32): 3 x 16384 x 128 floats = 24 MB total.
__device__ float g_qp[MROWS * HEAD];
__device__ float g_kp[MROWS * HEAD];
__device__ float g_vp[MROWS * HEAD];

// ---------------------------------------------------------------------------
// Kernel 1: projection GEMM  C[M,128] = A[M,1024] @ W[1024,128]
// 128x128 tile per block (N=128 covered in one tile), BK=8, 256 threads,
// each thread computes an 8x8 microtile.
// gridDim.x = M/128, gridDim.y = 3 (0: query@W_Q, 1: key@W_K, 2: value@W_V)
// ---------------------------------------------------------------------------
__global__ __launch_bounds__(256) void proj_kernel(
    const float* __restrict__ in_key,
    const float* __restrict__ in_query,
    const float* __restrict__ in_value,
    const float* __restrict__ w_q,
    const float* __restrict__ w_k,
    const float* __restrict__ w_v)
{
    const float* A;
    const float* W;
    float* C;
    int p = blockIdx.y;
    if (p == 0)      { A = in_query; W = w_q; C = g_qp; }
    else if (p == 1) { A = in_key;   W = w_k; C = g_kp; }
    else             { A = in_value; W = w_v; C = g_vp; }

    __shared__ float As[8][128];   // [k][m] (A transposed)
    __shared__ float Ws[8][128];   // [k][n]

    const int t  = threadIdx.x;
    const int ty = t >> 4;         // 0..15
    const int tx = t & 15;         // 0..15
    const int rowBase = blockIdx.x * 128;

    // A tile load mapping: 128 rows x 8 k, float4 per thread
    const int aRow = t >> 1;           // 0..127
    const int aK   = (t & 1) * 4;      // 0 or 4
    // W tile load mapping: 8 k-rows x 128 n, float4 per thread
    const int wRow = t >> 5;           // 0..7
    const int wCol = (t & 31) * 4;     // 0..124

    float acc[8][8];
#pragma unroll
    for (int i = 0; i < 8; i++)
#pragma unroll
        for (int j = 0; j < 8; j++) acc[i][j] = 0.0f;

    for (int k0 = 0; k0 < EMB; k0 += 8) {
        float4 av = *(const float4*)&A[(size_t)(rowBase + aRow) * EMB + k0 + aK];
        As[aK + 0][aRow] = av.x;
        As[aK + 1][aRow] = av.y;
        As[aK + 2][aRow] = av.z;
        As[aK + 3][aRow] = av.w;

        float4 wv4 = *(const float4*)&W[(size_t)(k0 + wRow) * HEAD + wCol];
        *(float4*)&Ws[wRow][wCol] = wv4;

        __syncthreads();

#pragma unroll
        for (int kk = 0; kk < 8; kk++) {
            float ra[8], rb[8];
#pragma unroll
            for (int i = 0; i < 8; i++) ra[i] = As[kk][ty * 8 + i];
#pragma unroll
            for (int j = 0; j < 8; j++) rb[j] = Ws[kk][tx * 8 + j];
#pragma unroll
            for (int i = 0; i < 8; i++)
#pragma unroll
                for (int j = 0; j < 8; j++)
                    acc[i][j] = fmaf(ra[i], rb[j], acc[i][j]);
        }
        __syncthreads();
    }

#pragma unroll
    for (int i = 0; i < 8; i++) {
        size_t r = (size_t)(rowBase + ty * 8 + i) * HEAD + tx * 8;
        *(float4*)&C[r]     = make_float4(acc[i][0], acc[i][1], acc[i][2], acc[i][3]);
        *(float4*)&C[r + 4] = make_float4(acc[i][4], acc[i][5], acc[i][6], acc[i][7]);
    }
}

// ---------------------------------------------------------------------------
// Kernel 2: fused causal retention  O = (Qp Kp^T  .* tril) Vp   per batch.
// One CTA per (128-query tile, batch). Q tile persists in smem (transposed
// [h][m]); loop over key tiles j <= qt:
//   S = Q K_j^T   (reg accum, contraction over h via smem)
//   mask diagonal tile, S -> smem transposed [n][m]
//   V_j -> smem (reusing K buffer), O += S V_j (contraction over n)
// 256 threads, 8x8 microtiles for both GEMMs.
// ---------------------------------------------------------------------------
#define LDS 132   // smem row stride in floats (pad, keeps float4 alignment: 132*4=528B)

__global__ __launch_bounds__(256) void retention_kernel(float* __restrict__ out)
{
    extern __shared__ float sm[];
    float* Qs  = sm;                 // [h][m]  128 x LDS
    float* KVs = sm + 128 * LDS;     // K phase: [h][n]; V phase: [n][h]
    float* Ss  = sm + 2 * 128 * LDS; // [n][m]

    const int qt = blockIdx.x;       // query tile 0..15
    const int b  = blockIdx.y;       // batch 0..7
    const int t  = threadIdx.x;
    const int ty = t >> 4;           // 0..15
    const int tx = t & 15;           // 0..15

    const size_t qRowBase = (size_t)b * SEQ + (size_t)qt * 128;

    // Load Q tile transposed into Qs[h][m]
    for (int u = t; u < 128 * 32; u += 256) {
        int m  = u >> 5;
        int h4 = (u & 31) * 4;
        float4 qv = *(const float4*)&g_qp[(qRowBase + m) * HEAD + h4];
        Qs[(h4 + 0) * LDS + m] = qv.x;
        Qs[(h4 + 1) * LDS + m] = qv.y;
        Qs[(h4 + 2) * LDS + m] = qv.z;
        Qs[(h4 + 3) * LDS + m] = qv.w;
    }

    float acc_o[8][8];
#pragma unroll
    for (int i = 0; i < 8; i++)
#pragma unroll
        for (int j = 0; j < 8; j++) acc_o[i][j] = 0.0f;

    for (int j = 0; j <= qt; j++) {
        __syncthreads();   // prev iter done with KVs/Ss; Q load visible (iter 0)

        // Load K_j transposed into KVs[h][n]
        const size_t kRowBase = (size_t)b * SEQ + (size_t)j * 128;
        for (int u = t; u < 128 * 32; u += 256) {
            int n  = u >> 5;
            int h4 = (u & 31) * 4;
            float4 kv = *(const float4*)&g_kp[(kRowBase + n) * HEAD + h4];
            KVs[(h4 + 0) * LDS + n] = kv.x;
            KVs[(h4 + 1) * LDS + n] = kv.y;
            KVs[(h4 + 2) * LDS + n] = kv.z;
            KVs[(h4 + 3) * LDS + n] = kv.w;
        }
        __syncthreads();

        // GEMM1: S[m][n] = sum_h Q[m][h] K[n][h]
        float s[8][8];
#pragma unroll
        for (int i = 0; i < 8; i++)
#pragma unroll
            for (int jj = 0; jj < 8; jj++) s[i][jj] = 0.0f;

#pragma unroll 4
        for (int h = 0; h < 128; h++) {
            float rq[8], rk[8];
#pragma unroll
            for (int i = 0; i < 8; i++)  rq[i]  = Qs[h * LDS + ty * 8 + i];
#pragma unroll
            for (int jj = 0; jj < 8; jj++) rk[jj] = KVs[h * LDS + tx * 8 + jj];
#pragma unroll
            for (int i = 0; i < 8; i++)
#pragma unroll
                for (int jj = 0; jj < 8; jj++)
                    s[i][jj] = fmaf(rq[i], rk[jj], s[i][jj]);
        }

        // Causal mask on the diagonal tile: keep when m >= n (global q >= k)
        if (j == qt) {
#pragma unroll
            for (int i = 0; i < 8; i++)
#pragma unroll
                for (int jj = 0; jj < 8; jj++)
                    if ((ty * 8 + i) < (tx * 8 + jj)) s[i][jj] = 0.0f;
        }

        // Write S transposed into Ss[n][m]
#pragma unroll
        for (int jj = 0; jj < 8; jj++)
#pragma unroll
            for (int i = 0; i < 8; i++)
                Ss[(tx * 8 + jj) * LDS + ty * 8 + i] = s[i][jj];

        __syncthreads();   // K reads + S writes complete before V overwrites KVs

        // Load V_j natural layout into KVs[n][h]
        for (int u = t; u < 128 * 32; u += 256) {
            int n  = u >> 5;
            int h4 = (u & 31) * 4;
            float4 vv = *(const float4*)&g_vp[(kRowBase + n) * HEAD + h4];
            *(float4*)&KVs[n * LDS + h4] = vv;
        }
        __syncthreads();

        // GEMM2: O[m][h] += sum_n S[m][n] V[n][h]
#pragma unroll 4
        for (int n = 0; n < 128; n++) {
            float rs[8], rv[8];
#pragma unroll
            for (int i = 0; i < 8; i++)  rs[i]  = Ss[n * LDS + ty * 8 + i];
#pragma unroll
            for (int jj = 0; jj < 8; jj++) rv[jj] = KVs[n * LDS + tx * 8 + jj];
#pragma unroll
            for (int i = 0; i < 8; i++)
#pragma unroll
                for (int jj = 0; jj < 8; jj++)
                    acc_o[i][jj] = fmaf(rs[i], rv[jj], acc_o[i][jj]);
        }
    }

    // Write output tile
#pragma unroll
    for (int i = 0; i < 8; i++) {
        size_t r = (qRowBase + ty * 8 + i) * HEAD + tx * 8;
        *(float4*)&out[r]     = make_float4(acc_o[i][0], acc_o[i][1], acc_o[i][2], acc_o[i][3]);
        *(float4*)&out[r + 4] = make_float4(acc_o[i][4], acc_o[i][5], acc_o[i][6], acc_o[i][7]);
    }
}

// ---------------------------------------------------------------------------
// Launch
// Inputs (metadata order): 0=key, 1=query, 2=value, 3=W_Q, 4=W_K, 5=W_V
// Output: (B, S, H) float32 = 2,097,152 floats
// ---------------------------------------------------------------------------
extern "C" void kernel_launch(void* const* d_in, const int* in_sizes, int n_in,
                              void* d_out, int out_size)
{
    const float* key   = (const float*)d_in[0];
    const float* query = (const float*)d_in[1];
    const float* value = (const float*)d_in[2];
    const float* w_q   = (const float*)d_in[3];
    const float* w_k   = (const float*)d_in[4];
    const float* w_v   = (const float*)d_in[5];
    float* out = (float*)d_out;

    // Projections: Qp = query@W_Q, Kp = key@W_K, Vp = value@W_V
    dim3 g1(MROWS / 128, 3);
    proj_kernel<<<g1, 256>>>(key, query, value, w_q, w_k, w_v);

    // Fused causal retention
    const int smemBytes = 3 * 128 * LDS * sizeof(float);  // 202,752 B
    static bool attr_set = false;
    // cudaFuncSetAttribute is idempotent & not a stream op; safe under capture.
    cudaFuncSetAttribute(retention_kernel,
                         cudaFuncAttributeMaxDynamicSharedMemorySize, smemBytes);
    (void)attr_set;

    dim3 g2(SEQ / 128, BATCH);
    retention_kernel<<<g2, 256, smemBytes>>>(out);
}

// round 3
// speedup vs baseline: 2.7591x; 2.7591x over previous
#include <cuda_runtime.h>
#include <cuda_bf16.h>
#include <cstdint>

// Problem dims
#define BATCH 8
#define SEQ   2048
#define EMB   1024
#define HEAD  128
#define MROWS (BATCH * SEQ)     // 16384
#define NTILES (MROWS / 128)    // 128
#define TILE_ELE (128 * 128)    // bf16 elements per 128x128 tile

// Pre-split bf16 projected tensors, row-major per 128x128 tile.
// Q tiles: [m][h];  K tiles: [n][h];  V tiles: TRANSPOSED [h][n].
__device__ __nv_bfloat16 g_q_hi[NTILES * TILE_ELE];
__device__ __nv_bfloat16 g_q_lo[NTILES * TILE_ELE];
__device__ __nv_bfloat16 g_k_hi[NTILES * TILE_ELE];
__device__ __nv_bfloat16 g_k_lo[NTILES * TILE_ELE];
__device__ __nv_bfloat16 g_v_hi[NTILES * TILE_ELE];
__device__ __nv_bfloat16 g_v_lo[NTILES * TILE_ELE];

// ---------------------------------------------------------------------------
// HMMA m16n8k16 bf16 (row.col), fp32 accumulate — family-generic sm_80+.
// ---------------------------------------------------------------------------
__device__ __forceinline__ void mma16816(float* c,
    uint32_t a0, uint32_t a1, uint32_t a2, uint32_t a3,
    uint32_t b0, uint32_t b1)
{
    asm volatile(
        "mma.sync.aligned.m16n8k16.row.col.f32.bf16.bf16.f32 "
        "{%0,%1,%2,%3}, {%4,%5,%6,%7}, {%8,%9}, {%0,%1,%2,%3};"
        : "+f"(c[0]), "+f"(c[1]), "+f"(c[2]), "+f"(c[3])
        : "r"(a0), "r"(a1), "r"(a2), "r"(a3), "r"(b0), "r"(b1));
}

// Split a pair of fp32 into packed bf16x2 hi and bf16x2 residual lo.
__device__ __forceinline__ void split2(float a0, float a1, uint32_t& hi, uint32_t& lo) {
    __nv_bfloat162 h = __float22bfloat162_rn(make_float2(a0, a1));
    float2 hf = __bfloat1622float2(h);
    __nv_bfloat162 l = __float22bfloat162_rn(make_float2(a0 - hf.x, a1 - hf.y));
    hi = *reinterpret_cast<uint32_t*>(&h);
    lo = *reinterpret_cast<uint32_t*>(&l);
}

// Warp-level GEMM: acc[4][4][4] += A(64x16K, rows mbase..) * B(32x16K, rows nbase..)^T
// A smem layout [row][k] stride STRIDE (bf16), B smem [col][k] stride STRIDE.
// STRIDE must be ≡ 8 (mod 64) for conflict-free fragment LDS.
template<int KSTEPS, int STRIDE>
__device__ __forceinline__ void warp_gemm(float acc[4][4][4],
    const __nv_bfloat16* __restrict__ As, const __nv_bfloat16* __restrict__ Bs,
    int mbase, int nbase, int g, int t)
{
#pragma unroll 2
    for (int ks = 0; ks < KSTEPS; ks++) {
        const int k0 = ks * 16 + t * 2;
        uint32_t af[4][4];
#pragma unroll
        for (int mt = 0; mt < 4; mt++) {
            const __nv_bfloat16* pa = As + (mbase + mt * 16 + g) * STRIDE + k0;
            af[mt][0] = *(const uint32_t*)(pa);
            af[mt][1] = *(const uint32_t*)(pa + 8 * STRIDE);
            af[mt][2] = *(const uint32_t*)(pa + 8);
            af[mt][3] = *(const uint32_t*)(pa + 8 * STRIDE + 8);
        }
#pragma unroll
        for (int nt = 0; nt < 4; nt++) {
            const __nv_bfloat16* pb = Bs + (nbase + nt * 8 + g) * STRIDE + k0;
            uint32_t b0 = *(const uint32_t*)(pb);
            uint32_t b1 = *(const uint32_t*)(pb + 8);
#pragma unroll
            for (int mt = 0; mt < 4; mt++)
                mma16816(acc[mt][nt], af[mt][0], af[mt][1], af[mt][2], af[mt][3], b0, b1);
        }
    }
}

// ---------------------------------------------------------------------------
// Kernel 1: projection GEMM  C[M,128] = A[M,1024] @ W[1024,128]  (HMMA split)
// gridDim.x = 128 (M tiles), gridDim.y = 3 (Q, K, V)
// ---------------------------------------------------------------------------
#define PKPAD 72
#define PBUF  (128 * PKPAD)

__global__ __launch_bounds__(256) void proj_tc(
    const float* __restrict__ in_key,
    const float* __restrict__ in_query,
    const float* __restrict__ in_value,
    const float* __restrict__ w_q,
    const float* __restrict__ w_k,
    const float* __restrict__ w_v)
{
    __shared__ __align__(16) __nv_bfloat16 Ahi[PBUF], Alo[PBUF], Bhi[PBUF], Blo[PBUF];

    const float* A;
    const float* W;
    const int p = blockIdx.y;
    if (p == 0)      { A = in_query; W = w_q; }
    else if (p == 1) { A = in_key;   W = w_k; }
    else             { A = in_value; W = w_v; }

    const int tid  = threadIdx.x;
    const int wid  = tid >> 5, lane = tid & 31;
    const int g    = lane >> 2, t = lane & 3;
    const int mbase = (wid & 1) * 64;
    const int nbase = (wid >> 1) * 32;
    const int tile = blockIdx.x;
    const int rowBase = tile * 128;

    float acc[4][4][4];
#pragma unroll
    for (int i = 0; i < 4; i++)
#pragma unroll
        for (int j = 0; j < 4; j++)
#pragma unroll
            for (int q = 0; q < 4; q++) acc[i][j][q] = 0.0f;

    for (int kb = 0; kb < 16; kb++) {
        const int k0 = kb * 64;
        __syncthreads();   // prior mma reads done

        // Convert A block [128][64] fp32 -> bf16 hi/lo
#pragma unroll
        for (int it = 0; it < 8; it++) {
            int u = tid + it * 256;
            int row = u >> 4, c4 = (u & 15) * 4;
            float4 v = *(const float4*)&A[(size_t)(rowBase + row) * EMB + k0 + c4];
            uint32_t h0, l0, h1, l1;
            split2(v.x, v.y, h0, l0);
            split2(v.z, v.w, h1, l1);
            *(uint2*)(Ahi + row * PKPAD + c4) = make_uint2(h0, h1);
            *(uint2*)(Alo + row * PKPAD + c4) = make_uint2(l0, l1);
        }
        // Convert + transpose W block [64][128] fp32 -> Bs[n][k] bf16 hi/lo
#pragma unroll
        for (int it = 0; it < 8; it++) {
            int u = tid + it * 256;
            int n = u & 127, kr = (u >> 7) * 4;
            float w0 = W[(size_t)(k0 + kr + 0) * HEAD + n];
            float w1 = W[(size_t)(k0 + kr + 1) * HEAD + n];
            float w2 = W[(size_t)(k0 + kr + 2) * HEAD + n];
            float w3 = W[(size_t)(k0 + kr + 3) * HEAD + n];
            uint32_t h0, l0, h1, l1;
            split2(w0, w1, h0, l0);
            split2(w2, w3, h1, l1);
            *(uint2*)(Bhi + n * PKPAD + kr) = make_uint2(h0, h1);
            *(uint2*)(Blo + n * PKPAD + kr) = make_uint2(l0, l1);
        }
        __syncthreads();

#pragma unroll 1
        for (int pr = 0; pr < 3; pr++) {
            const __nv_bfloat16* As = (pr == 2) ? Alo : Ahi;
            const __nv_bfloat16* Bs = (pr == 1) ? Blo : Bhi;
            warp_gemm<4, PKPAD>(acc, As, Bs, mbase, nbase, g, t);
        }
    }

    // Epilogue: split to bf16 hi/lo, store tiles.
    __nv_bfloat16 *dhi, *dlo;
    if (p == 0)      { dhi = g_q_hi; dlo = g_q_lo; }
    else if (p == 1) { dhi = g_k_hi; dlo = g_k_lo; }
    else             { dhi = g_v_hi; dlo = g_v_lo; }
    const size_t base = (size_t)tile * TILE_ELE;

    if (p != 2) {
        // natural [row][h]
#pragma unroll
        for (int mt = 0; mt < 4; mt++)
#pragma unroll
            for (int nt = 0; nt < 4; nt++) {
                int r0 = mbase + mt * 16 + g;
                int c  = nbase + nt * 8 + t * 2;
                uint32_t hi, lo;
                split2(acc[mt][nt][0], acc[mt][nt][1], hi, lo);
                *(uint32_t*)(dhi + base + (size_t)r0 * 128 + c) = hi;
                *(uint32_t*)(dlo + base + (size_t)r0 * 128 + c) = lo;
                split2(acc[mt][nt][2], acc[mt][nt][3], hi, lo);
                *(uint32_t*)(dhi + base + (size_t)(r0 + 8) * 128 + c) = hi;
                *(uint32_t*)(dlo + base + (size_t)(r0 + 8) * 128 + c) = lo;
            }
    } else {
        // V: transposed [h][n], scalar bf16 stores
#pragma unroll
        for (int mt = 0; mt < 4; mt++)
#pragma unroll
            for (int nt = 0; nt < 4; nt++) {
#pragma unroll
                for (int q = 0; q < 4; q++) {
                    int row = mbase + mt * 16 + g + (q >> 1) * 8;   // n index
                    int col = nbase + nt * 8 + t * 2 + (q & 1);     // h index
                    float v = acc[mt][nt][q];
                    __nv_bfloat16 h = __float2bfloat16(v);
                    __nv_bfloat16 l = __float2bfloat16(v - __bfloat162float(h));
                    dhi[base + (size_t)col * 128 + row] = h;
                    dlo[base + (size_t)col * 128 + row] = l;
                }
            }
    }
}

// ---------------------------------------------------------------------------
// Kernel 2: fused causal retention on HMMA.
// One CTA per (128-query tile, batch). O accumulates in registers across j.
// ---------------------------------------------------------------------------
#define KPAD 136
#define RBUF (128 * KPAD)                  // bf16 elements per smem buffer
#define SMR_BYTES (6 * RBUF * 2)           // 208,896 B

__device__ __forceinline__ void copy_tile(__nv_bfloat16* dst,
                                          const __nv_bfloat16* __restrict__ src) {
    const uint4* s = (const uint4*)src;
#pragma unroll
    for (int it = 0; it < 8; it++) {
        int u = threadIdx.x + it * 256;    // 2048 uint4 per tile
        int row = u >> 4, c = u & 15;
        ((uint4*)(dst + row * KPAD))[c] = s[u];
    }
}

__global__ __launch_bounds__(256) void retention_tc(float* __restrict__ out)
{
    extern __shared__ __align__(16) char smraw[];
    __nv_bfloat16* sm   = (__nv_bfloat16*)smraw;
    __nv_bfloat16* Qhi  = sm;
    __nv_bfloat16* Qlo  = sm + 1 * RBUF;
    __nv_bfloat16* KShi = sm + 2 * RBUF;   // K during GEMM1, then S for GEMM2
    __nv_bfloat16* KSlo = sm + 3 * RBUF;
    __nv_bfloat16* Vhi  = sm + 4 * RBUF;
    __nv_bfloat16* Vlo  = sm + 5 * RBUF;

    const int tid  = threadIdx.x;
    const int wid  = tid >> 5, lane = tid & 31;
    const int g    = lane >> 2, t = lane & 3;
    const int mbase = (wid & 1) * 64;
    const int nbase = (wid >> 1) * 32;
    const int qt = blockIdx.x, b = blockIdx.y;
    const int qtile = b * 16 + qt;

    copy_tile(Qhi, g_q_hi + (size_t)qtile * TILE_ELE);
    copy_tile(Qlo, g_q_lo + (size_t)qtile * TILE_ELE);

    float oacc[4][4][4];
#pragma unroll
    for (int i = 0; i < 4; i++)
#pragma unroll
        for (int j = 0; j < 4; j++)
#pragma unroll
            for (int q = 0; q < 4; q++) oacc[i][j][q] = 0.0f;

    for (int j = 0; j <= qt; j++) {
        __syncthreads();   // prev GEMM2 reads done (and Q copy visible on iter 0)

        const size_t kt = (size_t)(b * 16 + j) * TILE_ELE;
        copy_tile(KShi, g_k_hi + kt);
        copy_tile(KSlo, g_k_lo + kt);
        copy_tile(Vhi,  g_v_hi + kt);
        copy_tile(Vlo,  g_v_lo + kt);
        __syncthreads();

        // ---- GEMM1: S = Q K^T (3 split products) ----
        float sacc[4][4][4];
#pragma unroll
        for (int i = 0; i < 4; i++)
#pragma unroll
            for (int jj = 0; jj < 4; jj++)
#pragma unroll
                for (int q = 0; q < 4; q++) sacc[i][jj][q] = 0.0f;

#pragma unroll 1
        for (int pr = 0; pr < 3; pr++) {
            const __nv_bfloat16* As = (pr == 2) ? Qlo : Qhi;
            const __nv_bfloat16* Bs = (pr == 1) ? KSlo : KShi;
            warp_gemm<8, KPAD>(sacc, As, Bs, mbase, nbase, g, t);
        }

        // ---- causal mask on diagonal tile ----
        if (j == qt) {
#pragma unroll
            for (int mt = 0; mt < 4; mt++)
#pragma unroll
                for (int nt = 0; nt < 4; nt++) {
                    int r0 = mbase + mt * 16 + g;
                    int c0 = nbase + nt * 8 + t * 2;
                    if (c0     > r0)     sacc[mt][nt][0] = 0.0f;
                    if (c0 + 1 > r0)     sacc[mt][nt][1] = 0.0f;
                    if (c0     > r0 + 8) sacc[mt][nt][2] = 0.0f;
                    if (c0 + 1 > r0 + 8) sacc[mt][nt][3] = 0.0f;
                }
        }

        __syncthreads();   // all warps done reading K from KS buffers

        // ---- split S, store into KS buffers ----
#pragma unroll
        for (int mt = 0; mt < 4; mt++)
#pragma unroll
            for (int nt = 0; nt < 4; nt++) {
                int r0 = mbase + mt * 16 + g;
                int c  = nbase + nt * 8 + t * 2;
                uint32_t hi, lo;
                split2(sacc[mt][nt][0], sacc[mt][nt][1], hi, lo);
                *(uint32_t*)(KShi + r0 * KPAD + c) = hi;
                *(uint32_t*)(KSlo + r0 * KPAD + c) = lo;
                split2(sacc[mt][nt][2], sacc[mt][nt][3], hi, lo);
                *(uint32_t*)(KShi + (r0 + 8) * KPAD + c) = hi;
                *(uint32_t*)(KSlo + (r0 + 8) * KPAD + c) = lo;
            }
        __syncthreads();

        // ---- GEMM2: O += S V (3 split products), O persistent in regs ----
#pragma unroll 1
        for (int pr = 0; pr < 3; pr++) {
            const __nv_bfloat16* As = (pr == 2) ? KSlo : KShi;
            const __nv_bfloat16* Bs = (pr == 1) ? Vlo : Vhi;
            warp_gemm<8, KPAD>(oacc, As, Bs, mbase, nbase, g, t);
        }
    }

    // ---- epilogue: store O fp32 ----
    const size_t rowbase = (size_t)b * SEQ + (size_t)qt * 128;
#pragma unroll
    for (int mt = 0; mt < 4; mt++)
#pragma unroll
        for (int nt = 0; nt < 4; nt++) {
            int r0 = mbase + mt * 16 + g;
            int c  = nbase + nt * 8 + t * 2;
            *(float2*)&out[(rowbase + r0) * HEAD + c] =
                make_float2(oacc[mt][nt][0], oacc[mt][nt][1]);
            *(float2*)&out[(rowbase + r0 + 8) * HEAD + c] =
                make_float2(oacc[mt][nt][2], oacc[mt][nt][3]);
        }
}

// ---------------------------------------------------------------------------
// Launch
// Inputs: 0=key, 1=query, 2=value, 3=W_Q, 4=W_K, 5=W_V; output (B,S,H) fp32.
// ---------------------------------------------------------------------------
extern "C" void kernel_launch(void* const* d_in, const int* in_sizes, int n_in,
                              void* d_out, int out_size)
{
    const float* key   = (const float*)d_in[0];
    const float* query = (const float*)d_in[1];
    const float* value = (const float*)d_in[2];
    const float* w_q   = (const float*)d_in[3];
    const float* w_k   = (const float*)d_in[4];
    const float* w_v   = (const float*)d_in[5];
    float* out = (float*)d_out;

    dim3 g1(NTILES, 3);
    proj_tc<<<g1, 256>>>(key, query, value, w_q, w_k, w_v);

    cudaFuncSetAttribute(retention_tc,
                         cudaFuncAttributeMaxDynamicSharedMemorySize, SMR_BYTES);
    dim3 g2(SEQ / 128, BATCH);
    retention_tc<<<g2, 256, SMR_BYTES>>>(out);
}

// round 4
// speedup vs baseline: 3.9552x; 1.4336x over previous
#include <cuda_runtime.h>
#include <cuda_bf16.h>
#include <cstdint>

// Problem dims
#define BATCH 8
#define SEQ   2048
#define EMB   1024
#define HEAD  128
#define MROWS (BATCH * SEQ)     // 16384
#define NTILES (MROWS / 128)    // 128
#define TILE_ELE (128 * 128)    // elements per 128x128 tile

// Pre-split bf16 projected tensors, row-major per 128x128 tile.
// Q tiles: [m][h];  K tiles: [n][h];  V tiles: TRANSPOSED [h][n].
__device__ __nv_bfloat16 g_q_hi[NTILES * TILE_ELE];
__device__ __nv_bfloat16 g_q_lo[NTILES * TILE_ELE];
__device__ __nv_bfloat16 g_k_hi[NTILES * TILE_ELE];
__device__ __nv_bfloat16 g_k_lo[NTILES * TILE_ELE];
__device__ __nv_bfloat16 g_v_hi[NTILES * TILE_ELE];
__device__ __nv_bfloat16 g_v_lo[NTILES * TILE_ELE];

// Pre-split weights: [w][n][k] n-major, k contiguous (1024 per row)
__device__ __nv_bfloat16 g_w_hi[3 * 128 * 1024];
__device__ __nv_bfloat16 g_w_lo[3 * 128 * 1024];

// Partial O accumulators for split-K chunks (qt >= 8): [b][qt-8][m][h] fp32
__device__ float g_opart[BATCH * 8 * TILE_ELE];

// Chunk schedule: 24 chunks per batch, longest first.
__constant__ int c_qt[24] = {15,15,14, 7,14,13,13,12, 6,12,11,11,10, 5,10, 9, 9, 8, 4, 8, 3, 2, 1, 0};
__constant__ int c_j0[24] = { 0, 8, 0, 0, 8, 0, 7, 0, 0, 7, 0, 6, 0, 0, 6, 0, 5, 0, 0, 5, 0, 0, 0, 0};
__constant__ int c_j1[24] = { 8,16, 8, 8,15, 7,14, 7, 7,13, 6,12, 6, 6,11, 5,10, 5, 5, 9, 4, 3, 2, 1};

// ---------------------------------------------------------------------------
// PTX helpers (all family-generic: sm_80/75 baseline instructions)
// ---------------------------------------------------------------------------
__device__ __forceinline__ uint32_t smem_u32(const void* p) {
    uint32_t a;
    asm("{ .reg .u64 t; cvta.to.shared.u64 t, %1; cvt.u32.u64 %0, t; }"
        : "=r"(a) : "l"(p));
    return a;
}

__device__ __forceinline__ void mma16816(float* c,
    uint32_t a0, uint32_t a1, uint32_t a2, uint32_t a3,
    uint32_t b0, uint32_t b1)
{
    asm volatile(
        "mma.sync.aligned.m16n8k16.row.col.f32.bf16.bf16.f32 "
        "{%0,%1,%2,%3}, {%4,%5,%6,%7}, {%8,%9}, {%0,%1,%2,%3};"
        : "+f"(c[0]), "+f"(c[1]), "+f"(c[2]), "+f"(c[3])
        : "r"(a0), "r"(a1), "r"(a2), "r"(a3), "r"(b0), "r"(b1));
}

__device__ __forceinline__ void ldm_x4(uint32_t& r0, uint32_t& r1,
                                       uint32_t& r2, uint32_t& r3, uint32_t addr)
{
    asm volatile("ldmatrix.sync.aligned.m8n8.x4.shared.b16 {%0,%1,%2,%3}, [%4];"
                 : "=r"(r0), "=r"(r1), "=r"(r2), "=r"(r3) : "r"(addr));
}

#define CP_ASYNC16(dst, src) \
    asm volatile("cp.async.cg.shared.global [%0], [%1], 16;" :: "r"(dst), "l"(src))
#define CP_COMMIT() asm volatile("cp.async.commit_group;" ::: "memory")
#define CP_WAIT(n)  asm volatile("cp.async.wait_group %0;" :: "n"(n) : "memory")

// Split a pair of fp32 into packed bf16x2 hi and bf16x2 residual lo.
__device__ __forceinline__ void split2(float a0, float a1, uint32_t& hi, uint32_t& lo) {
    __nv_bfloat162 h = __float22bfloat162_rn(make_float2(a0, a1));
    float2 hf = __bfloat1622float2(h);
    __nv_bfloat162 l = __float22bfloat162_rn(make_float2(a0 - hf.x, a1 - hf.y));
    hi = *reinterpret_cast<uint32_t*>(&h);
    lo = *reinterpret_cast<uint32_t*>(&l);
}

// Warp GEMM via ldmatrix: acc[4][4][4] += A(64x16K rows mbase..) * B(32x16K rows nbase..)^T
// A smem [row][k] stride STRIDE bf16; B smem [col][k] stride STRIDE.
// STRIDE*2 mod 128 == 16 required (144 or 272 bytes) for conflict-free ldmatrix.
template<int KSTEPS, int STRIDE>
__device__ __forceinline__ void warp_gemm_ldm(float acc[4][4][4],
    uint32_t As, uint32_t Bs, int mbase, int nbase, int lane)
{
    const uint32_t a_lane = ((mbase + (lane & 15)) * STRIDE + (lane >> 4) * 8) * 2;
    const uint32_t b_lane = ((nbase + (lane & 7) + ((lane >> 4) << 3)) * STRIDE
                             + ((lane >> 3) & 1) * 8) * 2;
#pragma unroll 2
    for (int ks = 0; ks < KSTEPS; ks++) {
        uint32_t af[4][4];
#pragma unroll
        for (int mt = 0; mt < 4; mt++)
            ldm_x4(af[mt][0], af[mt][1], af[mt][2], af[mt][3],
                   As + a_lane + (uint32_t)(mt * 16 * STRIDE + ks * 16) * 2);
        uint32_t bf[2][4];
#pragma unroll
        for (int np = 0; np < 2; np++)
            ldm_x4(bf[np][0], bf[np][1], bf[np][2], bf[np][3],
                   Bs + b_lane + (uint32_t)(np * 16 * STRIDE + ks * 16) * 2);
#pragma unroll
        for (int mt = 0; mt < 4; mt++)
#pragma unroll
            for (int np = 0; np < 2; np++) {
                mma16816(acc[mt][2 * np],     af[mt][0], af[mt][1], af[mt][2], af[mt][3],
                         bf[np][0], bf[np][1]);
                mma16816(acc[mt][2 * np + 1], af[mt][0], af[mt][1], af[mt][2], af[mt][3],
                         bf[np][2], bf[np][3]);
            }
    }
}

// ---------------------------------------------------------------------------
// Kernel 0: pre-split W into bf16 hi/lo, layout [w][n][k]
// ---------------------------------------------------------------------------
__global__ __launch_bounds__(256) void prep_w(
    const float* __restrict__ wq, const float* __restrict__ wk,
    const float* __restrict__ wv)
{
    int u = blockIdx.x * 256 + threadIdx.x;      // pair id, 0..196607
    int w = u >> 16;
    int rem = u & 65535;
    int n = rem >> 9;
    int kp = (rem & 511) * 2;
    const float* W = (w == 0) ? wq : (w == 1) ? wk : wv;
    float w0 = W[(size_t)kp * HEAD + n];
    float w1 = W[(size_t)(kp + 1) * HEAD + n];
    uint32_t hi, lo;
    split2(w0, w1, hi, lo);
    size_t off = ((size_t)w * 128 + n) * 1024 + kp;
    *(uint32_t*)&g_w_hi[off] = hi;
    *(uint32_t*)&g_w_lo[off] = lo;
}

// ---------------------------------------------------------------------------
// Kernel 1: projection GEMM  C[M,128] = A[M,1024] @ W[1024,128]
// A staged through registers (LDG pipelined against MMA); W via cp.async
// double-buffer of pre-split bf16.
// ---------------------------------------------------------------------------
#define PKPAD 72
#define PBUF_B (128 * PKPAD * 2)   // bytes per bf16 buffer: 18432
// smem layout (bytes): Ahi 0, Alo 1*PBUF_B, Whi[0] 2*, Wlo[0] 3*, Whi[1] 4*, Wlo[1] 5*
#define PSM_TOTAL (6 * PBUF_B)     // 110592

__global__ __launch_bounds__(256) void proj_tc(
    const float* __restrict__ in_key,
    const float* __restrict__ in_query,
    const float* __restrict__ in_value)
{
    extern __shared__ __align__(16) char psm[];
    const uint32_t sb = smem_u32(psm);
    const uint32_t sAhi = sb, sAlo = sb + PBUF_B;

    const float* A;
    const int p = blockIdx.y;
    if (p == 0)      A = in_query;
    else if (p == 1) A = in_key;
    else             A = in_value;

    const int tid  = threadIdx.x;
    const int wid  = tid >> 5, lane = tid & 31;
    const int g    = lane >> 2, t = lane & 3;
    const int mbase = (wid & 1) * 64;
    const int nbase = (wid >> 1) * 32;
    const int tile = blockIdx.x;
    const int rowBase = tile * 128;

    // A staging mapping: 2048 float4 chunks, 16 per row
    const int aRow[8] = { (tid + 0*256) >> 4, (tid + 1*256) >> 4, (tid + 2*256) >> 4,
                          (tid + 3*256) >> 4, (tid + 4*256) >> 4, (tid + 5*256) >> 4,
                          (tid + 6*256) >> 4, (tid + 7*256) >> 4 };
    const int aC4 = (tid & 15) * 4;

    // W cp.async mapping: 1024 16B chunks per buffer, 8 per row
    const int wRow = tid >> 3;          // row for first 2 chunks handled per thread? use loop
    (void)wRow;

    float acc[4][4][4];
#pragma unroll
    for (int i = 0; i < 4; i++)
#pragma unroll
        for (int j = 0; j < 4; j++)
#pragma unroll
            for (int q = 0; q < 4; q++) acc[i][j][q] = 0.0f;

    const __nv_bfloat16* wsrc_hi = g_w_hi + (size_t)p * 128 * 1024;
    const __nv_bfloat16* wsrc_lo = g_w_lo + (size_t)p * 128 * 1024;

    // issue W(kb) into stage s
    auto cpa_w = [&](int kb, int s) {
        uint32_t dhi = sb + (2 + 2 * s) * PBUF_B;
        uint32_t dlo = dhi + PBUF_B;
#pragma unroll
        for (int it = 0; it < 4; it++) {
            int u = tid + it * 256;            // 0..1023
            int row = u >> 3, c = u & 7;
            uint32_t doff = (uint32_t)(row * PKPAD + c * 8) * 2;
            size_t soff = (size_t)row * 1024 + kb * 64 + c * 8;
            CP_ASYNC16(dhi + doff, (const char*)(wsrc_hi + soff));
            CP_ASYNC16(dlo + doff, (const char*)(wsrc_lo + soff));
        }
        CP_COMMIT();
    };

    // Prologue: W(0) -> stage 0; A(0) -> regs
    cpa_w(0, 0);
    float4 areg[8];
#pragma unroll
    for (int it = 0; it < 8; it++)
        areg[it] = *(const float4*)&A[(size_t)(rowBase + aRow[it]) * EMB + 0 + aC4];

    for (int kb = 0; kb < 16; kb++) {
        __syncthreads();   // mma(kb-1) finished: A smem + old W stage free

        // convert A regs -> STS bf16 hi/lo
#pragma unroll
        for (int it = 0; it < 8; it++) {
            uint32_t h0, l0, h1, l1;
            split2(areg[it].x, areg[it].y, h0, l0);
            split2(areg[it].z, areg[it].w, h1, l1);
            uint32_t doff = (uint32_t)(aRow[it] * PKPAD + aC4) * 2;
            asm volatile("st.shared.v2.b32 [%0], {%1,%2};" :: "r"(sAhi + doff), "r"(h0), "r"(h1));
            asm volatile("st.shared.v2.b32 [%0], {%1,%2};" :: "r"(sAlo + doff), "r"(l0), "r"(l1));
        }

        if (kb < 15) {
            // prefetch A(kb+1) into regs; W(kb+1) into other stage
            const int k0n = (kb + 1) * 64;
#pragma unroll
            for (int it = 0; it < 8; it++)
                areg[it] = *(const float4*)&A[(size_t)(rowBase + aRow[it]) * EMB + k0n + aC4];
            cpa_w(kb + 1, (kb + 1) & 1);
            CP_WAIT(1);          // W(kb) complete
        } else {
            CP_WAIT(0);
        }
        __syncthreads();         // A STS + W(kb) visible to all

        const uint32_t sWhi = sb + (2 + 2 * (kb & 1)) * PBUF_B;
        const uint32_t sWlo = sWhi + PBUF_B;
#pragma unroll 1
        for (int pr = 0; pr < 3; pr++) {
            uint32_t As = (pr == 2) ? sAlo : sAhi;
            uint32_t Bs = (pr == 1) ? sWlo : sWhi;
            warp_gemm_ldm<4, PKPAD>(acc, As, Bs, mbase, nbase, lane);
        }
    }

    // Epilogue: split to bf16 hi/lo, store tiles.
    __nv_bfloat16 *dhi, *dlo;
    if (p == 0)      { dhi = g_q_hi; dlo = g_q_lo; }
    else if (p == 1) { dhi = g_k_hi; dlo = g_k_lo; }
    else             { dhi = g_v_hi; dlo = g_v_lo; }
    const size_t base = (size_t)tile * TILE_ELE;

    if (p != 2) {
#pragma unroll
        for (int mt = 0; mt < 4; mt++)
#pragma unroll
            for (int nt = 0; nt < 4; nt++) {
                int r0 = mbase + mt * 16 + g;
                int c  = nbase + nt * 8 + t * 2;
                uint32_t hi, lo;
                split2(acc[mt][nt][0], acc[mt][nt][1], hi, lo);
                *(uint32_t*)(dhi + base + (size_t)r0 * 128 + c) = hi;
                *(uint32_t*)(dlo + base + (size_t)r0 * 128 + c) = lo;
                split2(acc[mt][nt][2], acc[mt][nt][3], hi, lo);
                *(uint32_t*)(dhi + base + (size_t)(r0 + 8) * 128 + c) = hi;
                *(uint32_t*)(dlo + base + (size_t)(r0 + 8) * 128 + c) = lo;
            }
    } else {
        // V: transposed [h][n]
#pragma unroll
        for (int mt = 0; mt < 4; mt++)
#pragma unroll
            for (int nt = 0; nt < 4; nt++)
#pragma unroll
                for (int q = 0; q < 4; q++) {
                    int row = mbase + mt * 16 + g + (q >> 1) * 8;   // n index
                    int col = nbase + nt * 8 + t * 2 + (q & 1);     // h index
                    float v = acc[mt][nt][q];
                    __nv_bfloat16 h = __float2bfloat16(v);
                    __nv_bfloat16 l = __float2bfloat16(v - __bfloat162float(h));
                    dhi[base + (size_t)col * 128 + row] = h;
                    dlo[base + (size_t)col * 128 + row] = l;
                }
    }
}

// ---------------------------------------------------------------------------
// Kernel 2: fused causal retention, chunked split-K over key tiles.
// ---------------------------------------------------------------------------
#define KPAD 136
#define RB (128 * KPAD * 2)                 // bytes per buffer: 34816
// buffers: Qhi 0, Qlo RB, KShi 2RB, KSlo 3RB, Vhi 4RB, Vlo 5RB
#define SMR_BYTES (6 * RB)                  // 208896

__device__ __forceinline__ void cpa_tile(uint32_t dst, const __nv_bfloat16* __restrict__ src,
                                         int tid) {
#pragma unroll
    for (int it = 0; it < 8; it++) {
        int u = tid + it * 256;             // 0..2047 (16B chunks)
        int row = u >> 4, c = u & 15;
        CP_ASYNC16(dst + (uint32_t)(row * KPAD + c * 8) * 2, (const char*)src + (size_t)u * 16);
    }
}

__global__ __launch_bounds__(256) void retention_tc(float* __restrict__ out)
{
    extern __shared__ __align__(16) char smraw[];
    const uint32_t sb = smem_u32(smraw);
    const uint32_t sQhi = sb,        sQlo = sb + RB;
    const uint32_t sKShi = sb + 2*RB, sKSlo = sb + 3*RB;
    const uint32_t sVhi = sb + 4*RB, sVlo = sb + 5*RB;
    char* smc = smraw;

    const int tid  = threadIdx.x;
    const int wid  = tid >> 5, lane = tid & 31;
    const int g    = lane >> 2, t = lane & 3;
    const int mbase = (wid & 1) * 64;
    const int nbase = (wid >> 1) * 32;

    const int b   = blockIdx.x;
    const int cid = blockIdx.y;
    const int qt  = c_qt[cid];
    const int j0  = c_j0[cid];
    const int j1  = c_j1[cid];
    const bool partial = (j1 != qt + 1);
    const int qtile = b * 16 + qt;

    // Prologue: Q (group), K(j0) (group), V(j0) (group)
    cpa_tile(sQhi, g_q_hi + (size_t)qtile * TILE_ELE, tid);
    cpa_tile(sQlo, g_q_lo + (size_t)qtile * TILE_ELE, tid);
    CP_COMMIT();
    {
        const size_t kt = (size_t)(b * 16 + j0) * TILE_ELE;
        cpa_tile(sKShi, g_k_hi + kt, tid);
        cpa_tile(sKSlo, g_k_lo + kt, tid);
        CP_COMMIT();
        cpa_tile(sVhi, g_v_hi + kt, tid);
        cpa_tile(sVlo, g_v_lo + kt, tid);
        CP_COMMIT();
    }
    CP_WAIT(1);          // Q + K arrived
    __syncthreads();

    float oacc[4][4][4];
#pragma unroll
    for (int i = 0; i < 4; i++)
#pragma unroll
        for (int j = 0; j < 4; j++)
#pragma unroll
            for (int q = 0; q < 4; q++) oacc[i][j][q] = 0.0f;

    for (int j = j0; j < j1; j++) {
        // ---- GEMM1: S = Q K^T (3 split products) ----
        float sacc[4][4][4];
#pragma unroll
        for (int i = 0; i < 4; i++)
#pragma unroll
            for (int jj = 0; jj < 4; jj++)
#pragma unroll
                for (int q = 0; q < 4; q++) sacc[i][jj][q] = 0.0f;

#pragma unroll 1
        for (int pr = 0; pr < 3; pr++) {
            uint32_t As = (pr == 2) ? sQlo : sQhi;
            uint32_t Bs = (pr == 1) ? sKSlo : sKShi;
            warp_gemm_ldm<8, KPAD>(sacc, As, Bs, mbase, nbase, lane);
        }

        // ---- causal mask on diagonal tile ----
        if (j == qt) {
#pragma unroll
            for (int mt = 0; mt < 4; mt++)
#pragma unroll
                for (int nt = 0; nt < 4; nt++) {
                    int r0 = mbase + mt * 16 + g;
                    int c0 = nbase + nt * 8 + t * 2;
                    if (c0     > r0)     sacc[mt][nt][0] = 0.0f;
                    if (c0 + 1 > r0)     sacc[mt][nt][1] = 0.0f;
                    if (c0     > r0 + 8) sacc[mt][nt][2] = 0.0f;
                    if (c0 + 1 > r0 + 8) sacc[mt][nt][3] = 0.0f;
                }
        }

        __syncthreads();   // all warps done reading K

        // ---- split S -> KS buffers ----
#pragma unroll
        for (int mt = 0; mt < 4; mt++)
#pragma unroll
            for (int nt = 0; nt < 4; nt++) {
                int r0 = mbase + mt * 16 + g;
                int c  = nbase + nt * 8 + t * 2;
                uint32_t hi, lo;
                split2(sacc[mt][nt][0], sacc[mt][nt][1], hi, lo);
                *(uint32_t*)(smc + sKShi - sb + (r0 * KPAD + c) * 2) = hi;
                *(uint32_t*)(smc + sKSlo - sb + (r0 * KPAD + c) * 2) = lo;
                split2(sacc[mt][nt][2], sacc[mt][nt][3], hi, lo);
                *(uint32_t*)(smc + sKShi - sb + ((r0 + 8) * KPAD + c) * 2) = hi;
                *(uint32_t*)(smc + sKSlo - sb + ((r0 + 8) * KPAD + c) * 2) = lo;
            }

        CP_WAIT(0);        // V(j) arrived (this thread's groups all done)
        __syncthreads();   // S + V visible to all

        // ---- GEMM2: O += S V ----
#pragma unroll 1
        for (int pr = 0; pr < 3; pr++) {
            uint32_t As = (pr == 2) ? sKSlo : sKShi;
            uint32_t Bs = (pr == 1) ? sVlo : sVhi;
            warp_gemm_ldm<8, KPAD>(oacc, As, Bs, mbase, nbase, lane);
        }

        if (j + 1 < j1) {
            __syncthreads();   // S/V reads done before overwrite
            const size_t kt = (size_t)(b * 16 + j + 1) * TILE_ELE;
            cpa_tile(sKShi, g_k_hi + kt, tid);
            cpa_tile(sKSlo, g_k_lo + kt, tid);
            CP_COMMIT();
            cpa_tile(sVhi, g_v_hi + kt, tid);
            cpa_tile(sVlo, g_v_lo + kt, tid);
            CP_COMMIT();
            CP_WAIT(1);        // next K ready; V in flight
            __syncthreads();
        }
    }

    // ---- epilogue ----
    if (!partial) {
        const size_t rowbase = (size_t)b * SEQ + (size_t)qt * 128;
#pragma unroll
        for (int mt = 0; mt < 4; mt++)
#pragma unroll
            for (int nt = 0; nt < 4; nt++) {
                int r0 = mbase + mt * 16 + g;
                int c  = nbase + nt * 8 + t * 2;
                *(float2*)&out[(rowbase + r0) * HEAD + c] =
                    make_float2(oacc[mt][nt][0], oacc[mt][nt][1]);
                *(float2*)&out[(rowbase + r0 + 8) * HEAD + c] =
                    make_float2(oacc[mt][nt][2], oacc[mt][nt][3]);
            }
    } else {
        float* dst = g_opart + (size_t)(b * 8 + (qt - 8)) * TILE_ELE;
#pragma unroll
        for (int mt = 0; mt < 4; mt++)
#pragma unroll
            for (int nt = 0; nt < 4; nt++) {
                int r0 = mbase + mt * 16 + g;
                int c  = nbase + nt * 8 + t * 2;
                *(float2*)&dst[(size_t)r0 * HEAD + c] =
                    make_float2(oacc[mt][nt][0], oacc[mt][nt][1]);
                *(float2*)&dst[(size_t)(r0 + 8) * HEAD + c] =
                    make_float2(oacc[mt][nt][2], oacc[mt][nt][3]);
            }
    }
}

// ---------------------------------------------------------------------------
// Kernel 3: add partial O chunks into out (qt >= 8 only).
// ---------------------------------------------------------------------------
__global__ __launch_bounds__(256) void reduce_partials(float* __restrict__ out)
{
    int gid = blockIdx.x * 256 + threadIdx.x;   // 0..262143 float4 ids
    int tile = gid >> 12;                       // 4096 float4 per tile
    int w = gid & 4095;
    int b = tile >> 3, qti = tile & 7;
    float4* o = (float4*)(out + ((size_t)b * SEQ + (size_t)(qti + 8) * 128) * HEAD) + w;
    const float4* p = (const float4*)(g_opart + (size_t)tile * TILE_ELE) + w;
    float4 ov = *o, pv = *p;
    ov.x += pv.x; ov.y += pv.y; ov.z += pv.z; ov.w += pv.w;
    *o = ov;
}

// ---------------------------------------------------------------------------
// Launch
// Inputs: 0=key, 1=query, 2=value, 3=W_Q, 4=W_K, 5=W_V; output (B,S,H) fp32.
// ---------------------------------------------------------------------------
extern "C" void kernel_launch(void* const* d_in, const int* in_sizes, int n_in,
                              void* d_out, int out_size)
{
    const float* key   = (const float*)d_in[0];
    const float* query = (const float*)d_in[1];
    const float* value = (const float*)d_in[2];
    const float* w_q   = (const float*)d_in[3];
    const float* w_k   = (const float*)d_in[4];
    const float* w_v   = (const float*)d_in[5];
    float* out = (float*)d_out;

    prep_w<<<768, 256>>>(w_q, w_k, w_v);

    cudaFuncSetAttribute(proj_tc,
                         cudaFuncAttributeMaxDynamicSharedMemorySize, PSM_TOTAL);
    dim3 g1(NTILES, 3);
    proj_tc<<<g1, 256, PSM_TOTAL>>>(key, query, value);

    cudaFuncSetAttribute(retention_tc,
                         cudaFuncAttributeMaxDynamicSharedMemorySize, SMR_BYTES);
    dim3 g2(BATCH, 24);
    retention_tc<<<g2, 256, SMR_BYTES>>>(out);

    reduce_partials<<<1024, 256>>>(out);
}

// round 5
// speedup vs baseline: 4.0526x; 1.0246x over previous
#include <cuda_runtime.h>
#include <cuda_bf16.h>
#include <cstdint>

// Problem dims
#define BATCH 8
#define SEQ   2048
#define EMB   1024
#define HEAD  128
#define MROWS (BATCH * SEQ)     // 16384
#define NTILES (MROWS / 128)    // 128
#define TILE_ELE (128 * 128)

// Pre-split bf16 projected tensors, row-major per 128x128 tile.
// Q tiles: [m][h];  K tiles: [n][h];  V tiles: TRANSPOSED [h][n].
__device__ __nv_bfloat16 g_q_hi[NTILES * TILE_ELE];
__device__ __nv_bfloat16 g_q_lo[NTILES * TILE_ELE];
__device__ __nv_bfloat16 g_k_hi[NTILES * TILE_ELE];
__device__ __nv_bfloat16 g_k_lo[NTILES * TILE_ELE];
__device__ __nv_bfloat16 g_v_hi[NTILES * TILE_ELE];
__device__ __nv_bfloat16 g_v_lo[NTILES * TILE_ELE];

// Pre-split weights: [w][n][k], k contiguous
__device__ __nv_bfloat16 g_w_hi[3 * 128 * 1024];
__device__ __nv_bfloat16 g_w_lo[3 * 128 * 1024];

// Partial O accumulators for split-K chunks (qt >= 8)
__device__ float g_opart[BATCH * 8 * TILE_ELE];

// Chunk schedule: 24 chunks per batch, longest first.
__constant__ int c_qt[24] = {15,15,14, 7,14,13,13,12, 6,12,11,11,10, 5,10, 9, 9, 8, 4, 8, 3, 2, 1, 0};
__constant__ int c_j0[24] = { 0, 8, 0, 0, 8, 0, 7, 0, 0, 7, 0, 6, 0, 0, 6, 0, 5, 0, 0, 5, 0, 0, 0, 0};
__constant__ int c_j1[24] = { 8,16, 8, 8,15, 7,14, 7, 7,13, 6,12, 6, 6,11, 5,10, 5, 5, 9, 4, 3, 2, 1};

// ---------------------------------------------------------------------------
// PTX helpers (family-generic)
// ---------------------------------------------------------------------------
__device__ __forceinline__ uint32_t smem_u32(const void* p) {
    uint32_t a;
    asm("{ .reg .u64 t; cvta.to.shared.u64 t, %1; cvt.u32.u64 %0, t; }"
        : "=r"(a) : "l"(p));
    return a;
}

__device__ __forceinline__ void mma16816(float* c,
    uint32_t a0, uint32_t a1, uint32_t a2, uint32_t a3,
    uint32_t b0, uint32_t b1)
{
    asm volatile(
        "mma.sync.aligned.m16n8k16.row.col.f32.bf16.bf16.f32 "
        "{%0,%1,%2,%3}, {%4,%5,%6,%7}, {%8,%9}, {%0,%1,%2,%3};"
        : "+f"(c[0]), "+f"(c[1]), "+f"(c[2]), "+f"(c[3])
        : "r"(a0), "r"(a1), "r"(a2), "r"(a3), "r"(b0), "r"(b1));
}

__device__ __forceinline__ void ldm_x4(uint32_t& r0, uint32_t& r1,
                                       uint32_t& r2, uint32_t& r3, uint32_t addr)
{
    asm volatile("ldmatrix.sync.aligned.m8n8.x4.shared.b16 {%0,%1,%2,%3}, [%4];"
                 : "=r"(r0), "=r"(r1), "=r"(r2), "=r"(r3) : "r"(addr));
}

#define CP_ASYNC16(dst, src) \
    asm volatile("cp.async.cg.shared.global [%0], [%1], 16;" :: "r"(dst), "l"(src))
#define CP_COMMIT() asm volatile("cp.async.commit_group;" ::: "memory")
#define CP_WAIT(n)  asm volatile("cp.async.wait_group %0;" :: "n"(n) : "memory")

__device__ __forceinline__ void split2(float a0, float a1, uint32_t& hi, uint32_t& lo) {
    __nv_bfloat162 h = __float22bfloat162_rn(make_float2(a0, a1));
    float2 hf = __bfloat1622float2(h);
    __nv_bfloat162 l = __float22bfloat162_rn(make_float2(a0 - hf.x, a1 - hf.y));
    hi = *reinterpret_cast<uint32_t*>(&h);
    lo = *reinterpret_cast<uint32_t*>(&l);
}

// ---------------------------------------------------------------------------
// Kernel 0: pre-split W into bf16 hi/lo, layout [w][n][k]
// ---------------------------------------------------------------------------
__global__ __launch_bounds__(256) void prep_w(
    const float* __restrict__ wq, const float* __restrict__ wk,
    const float* __restrict__ wv)
{
    int u = blockIdx.x * 256 + threadIdx.x;
    int w = u >> 16;
    int rem = u & 65535;
    int n = rem >> 9;
    int kp = (rem & 511) * 2;
    const float* W = (w == 0) ? wq : (w == 1) ? wk : wv;
    float w0 = W[(size_t)kp * HEAD + n];
    float w1 = W[(size_t)(kp + 1) * HEAD + n];
    uint32_t hi, lo;
    split2(w0, w1, hi, lo);
    size_t off = ((size_t)w * 128 + n) * 1024 + kp;
    *(uint32_t*)&g_w_hi[off] = hi;
    *(uint32_t*)&g_w_lo[off] = lo;
}

// ---------------------------------------------------------------------------
// Old-style warp GEMM (64x32 warp tile) used by proj only.
// ---------------------------------------------------------------------------
template<int KSTEPS, int STRIDE>
__device__ __forceinline__ void warp_gemm_ldm(float acc[4][4][4],
    uint32_t As, uint32_t Bs, int mbase, int nbase, int lane)
{
    const uint32_t a_lane = ((mbase + (lane & 15)) * STRIDE + (lane >> 4) * 8) * 2;
    const uint32_t b_lane = ((nbase + (lane & 7) + ((lane >> 4) << 3)) * STRIDE
                             + ((lane >> 3) & 1) * 8) * 2;
#pragma unroll 2
    for (int ks = 0; ks < KSTEPS; ks++) {
        uint32_t af[4][4];
#pragma unroll
        for (int mt = 0; mt < 4; mt++)
            ldm_x4(af[mt][0], af[mt][1], af[mt][2], af[mt][3],
                   As + a_lane + (uint32_t)(mt * 16 * STRIDE + ks * 16) * 2);
        uint32_t bf[2][4];
#pragma unroll
        for (int np = 0; np < 2; np++)
            ldm_x4(bf[np][0], bf[np][1], bf[np][2], bf[np][3],
                   Bs + b_lane + (uint32_t)(np * 16 * STRIDE + ks * 16) * 2);
#pragma unroll
        for (int mt = 0; mt < 4; mt++)
#pragma unroll
            for (int np = 0; np < 2; np++) {
                mma16816(acc[mt][2 * np],     af[mt][0], af[mt][1], af[mt][2], af[mt][3],
                         bf[np][0], bf[np][1]);
                mma16816(acc[mt][2 * np + 1], af[mt][0], af[mt][1], af[mt][2], af[mt][3],
                         bf[np][2], bf[np][3]);
            }
    }
}

// ---------------------------------------------------------------------------
// Kernel 1: projection GEMM (unchanged from round 4)
// ---------------------------------------------------------------------------
#define PKPAD 72
#define PBUF_B (128 * PKPAD * 2)
#define PSM_TOTAL (6 * PBUF_B)

__global__ __launch_bounds__(256) void proj_tc(
    const float* __restrict__ in_key,
    const float* __restrict__ in_query,
    const float* __restrict__ in_value)
{
    extern __shared__ __align__(16) char psm[];
    const uint32_t sb = smem_u32(psm);
    const uint32_t sAhi = sb, sAlo = sb + PBUF_B;

    const float* A;
    const int p = blockIdx.y;
    if (p == 0)      A = in_query;
    else if (p == 1) A = in_key;
    else             A = in_value;

    const int tid  = threadIdx.x;
    const int wid  = tid >> 5, lane = tid & 31;
    const int g    = lane >> 2, t = lane & 3;
    const int mbase = (wid & 1) * 64;
    const int nbase = (wid >> 1) * 32;
    const int tile = blockIdx.x;
    const int rowBase = tile * 128;

    const int aRow0 = tid >> 4;
    const int aC4 = (tid & 15) * 4;

    float acc[4][4][4];
#pragma unroll
    for (int i = 0; i < 4; i++)
#pragma unroll
        for (int j = 0; j < 4; j++)
#pragma unroll
            for (int q = 0; q < 4; q++) acc[i][j][q] = 0.0f;

    const __nv_bfloat16* wsrc_hi = g_w_hi + (size_t)p * 128 * 1024;
    const __nv_bfloat16* wsrc_lo = g_w_lo + (size_t)p * 128 * 1024;

    auto cpa_w = [&](int kb, int s) {
        uint32_t dhi = sb + (2 + 2 * s) * PBUF_B;
        uint32_t dlo = dhi + PBUF_B;
#pragma unroll
        for (int it = 0; it < 4; it++) {
            int u = tid + it * 256;
            int row = u >> 3, c = u & 7;
            uint32_t doff = (uint32_t)(row * PKPAD + c * 8) * 2;
            size_t soff = (size_t)row * 1024 + kb * 64 + c * 8;
            CP_ASYNC16(dhi + doff, (const char*)(wsrc_hi + soff));
            CP_ASYNC16(dlo + doff, (const char*)(wsrc_lo + soff));
        }
        CP_COMMIT();
    };

    cpa_w(0, 0);
    float4 areg[8];
#pragma unroll
    for (int it = 0; it < 8; it++)
        areg[it] = *(const float4*)&A[(size_t)(rowBase + aRow0 + it * 16) * EMB + aC4];

    for (int kb = 0; kb < 16; kb++) {
        __syncthreads();

#pragma unroll
        for (int it = 0; it < 8; it++) {
            uint32_t h0, l0, h1, l1;
            split2(areg[it].x, areg[it].y, h0, l0);
            split2(areg[it].z, areg[it].w, h1, l1);
            uint32_t doff = (uint32_t)((aRow0 + it * 16) * PKPAD + aC4) * 2;
            asm volatile("st.shared.v2.b32 [%0], {%1,%2};" :: "r"(sAhi + doff), "r"(h0), "r"(h1));
            asm volatile("st.shared.v2.b32 [%0], {%1,%2};" :: "r"(sAlo + doff), "r"(l0), "r"(l1));
        }

        if (kb < 15) {
            const int k0n = (kb + 1) * 64;
#pragma unroll
            for (int it = 0; it < 8; it++)
                areg[it] = *(const float4*)&A[(size_t)(rowBase + aRow0 + it * 16) * EMB + k0n + aC4];
            cpa_w(kb + 1, (kb + 1) & 1);
            CP_WAIT(1);
        } else {
            CP_WAIT(0);
        }
        __syncthreads();

        const uint32_t sWhi = sb + (2 + 2 * (kb & 1)) * PBUF_B;
        const uint32_t sWlo = sWhi + PBUF_B;
#pragma unroll 1
        for (int pr = 0; pr < 3; pr++) {
            uint32_t As = (pr == 2) ? sAlo : sAhi;
            uint32_t Bs = (pr == 1) ? sWlo : sWhi;
            warp_gemm_ldm<4, PKPAD>(acc, As, Bs, mbase, nbase, lane);
        }
    }

    __nv_bfloat16 *dhi, *dlo;
    if (p == 0)      { dhi = g_q_hi; dlo = g_q_lo; }
    else if (p == 1) { dhi = g_k_hi; dlo = g_k_lo; }
    else             { dhi = g_v_hi; dlo = g_v_lo; }
    const size_t base = (size_t)tile * TILE_ELE;

    if (p != 2) {
#pragma unroll
        for (int mt = 0; mt < 4; mt++)
#pragma unroll
            for (int nt = 0; nt < 4; nt++) {
                int r0 = mbase + mt * 16 + g;
                int c  = nbase + nt * 8 + t * 2;
                uint32_t hi, lo;
                split2(acc[mt][nt][0], acc[mt][nt][1], hi, lo);
                *(uint32_t*)(dhi + base + (size_t)r0 * 128 + c) = hi;
                *(uint32_t*)(dlo + base + (size_t)r0 * 128 + c) = lo;
                split2(acc[mt][nt][2], acc[mt][nt][3], hi, lo);
                *(uint32_t*)(dhi + base + (size_t)(r0 + 8) * 128 + c) = hi;
                *(uint32_t*)(dlo + base + (size_t)(r0 + 8) * 128 + c) = lo;
            }
    } else {
#pragma unroll
        for (int mt = 0; mt < 4; mt++)
#pragma unroll
            for (int nt = 0; nt < 4; nt++)
#pragma unroll
                for (int q = 0; q < 4; q++) {
                    int row = mbase + mt * 16 + g + (q >> 1) * 8;
                    int col = nbase + nt * 8 + t * 2 + (q & 1);
                    float v = acc[mt][nt][q];
                    __nv_bfloat16 h = __float2bfloat16(v);
                    __nv_bfloat16 l = __float2bfloat16(v - __bfloat162float(h));
                    dhi[base + (size_t)col * 128 + row] = h;
                    dlo[base + (size_t)col * 128 + row] = l;
                }
    }
}

// ---------------------------------------------------------------------------
// Kernel 2: fused causal retention. Warp tile m16 x n128; S stays in registers
// between GEMM1 and GEMM2 (C-fragment == A-fragment layout identity).
// ---------------------------------------------------------------------------
#define KPAD 136
#define RB (128 * KPAD * 2)                 // 34816 B per buffer
#define SMR_BYTES (6 * RB)                  // 208896

__device__ __forceinline__ void cpa_tile(uint32_t dst, const __nv_bfloat16* __restrict__ src,
                                         int tid) {
#pragma unroll
    for (int it = 0; it < 8; it++) {
        int u = tid + it * 256;
        int row = u >> 4, c = u & 15;
        CP_ASYNC16(dst + (uint32_t)(row * KPAD + c * 8) * 2, (const char*)src + (size_t)u * 16);
    }
}

__global__ __launch_bounds__(256) void retention_tc(float* __restrict__ out)
{
    extern __shared__ __align__(16) char smraw[];
    const uint32_t sb = smem_u32(smraw);
    const uint32_t sQhi = sb,         sQlo = sb + RB;
    const uint32_t sKhi = sb + 2*RB,  sKlo = sb + 3*RB;
    const uint32_t sVhi = sb + 4*RB,  sVlo = sb + 5*RB;

    const int tid  = threadIdx.x;
    const int wid  = tid >> 5, lane = tid & 31;
    const int g    = lane >> 2, t = lane & 3;

    const int b   = blockIdx.x;
    const int cid = blockIdx.y;
    const int qt  = c_qt[cid];
    const int j0  = c_j0[cid];
    const int j1  = c_j1[cid];
    const bool partial = (j1 != qt + 1);
    const int qtile = b * 16 + qt;

    // ldmatrix lane addresses (byte offsets within a buffer)
    // A (m16k16 x4): rows 16*wid + (lane&15), col-half (lane>>4)*8
    const uint32_t a_lane = (uint32_t)((16 * wid + (lane & 15)) * KPAD + (lane >> 4) * 8) * 2;
    // B (n16k16 x4): rows (lane&7) + ((lane>>4)<<3), col-half ((lane>>3)&1)*8
    const uint32_t b_lane = (uint32_t)(((lane & 7) + ((lane >> 4) << 3)) * KPAD
                                       + ((lane >> 3) & 1) * 8) * 2;

    // Prologue: Q, K(j0), V(j0)
    cpa_tile(sQhi, g_q_hi + (size_t)qtile * TILE_ELE, tid);
    cpa_tile(sQlo, g_q_lo + (size_t)qtile * TILE_ELE, tid);
    CP_COMMIT();
    {
        const size_t kt = (size_t)(b * 16 + j0) * TILE_ELE;
        cpa_tile(sKhi, g_k_hi + kt, tid);
        cpa_tile(sKlo, g_k_lo + kt, tid);
        CP_COMMIT();
        cpa_tile(sVhi, g_v_hi + kt, tid);
        cpa_tile(sVlo, g_v_lo + kt, tid);
        CP_COMMIT();
    }
    CP_WAIT(1);          // Q + K arrived (V in flight)
    __syncthreads();

    float oacc[16][4];
#pragma unroll
    for (int i = 0; i < 16; i++)
#pragma unroll
        for (int q = 0; q < 4; q++) oacc[i][q] = 0.0f;

    for (int j = j0; j < j1; j++) {
        // ================= GEMM1: S[16 x 128] = Q K^T (3 products) ==========
        float sacc[16][4];
#pragma unroll
        for (int i = 0; i < 16; i++)
#pragma unroll
            for (int q = 0; q < 4; q++) sacc[i][q] = 0.0f;

#pragma unroll 2
        for (int ks = 0; ks < 8; ks++) {
            const uint32_t kso = (uint32_t)(ks * 16) * 2;
            uint32_t ah[4], al[4];
            ldm_x4(ah[0], ah[1], ah[2], ah[3], sQhi + a_lane + kso);
            ldm_x4(al[0], al[1], al[2], al[3], sQlo + a_lane + kso);
#pragma unroll
            for (int nb = 0; nb < 8; nb++) {
                const uint32_t boff = b_lane + (uint32_t)(nb * 16 * KPAD) * 2 + kso;
                uint32_t bh[4];
                ldm_x4(bh[0], bh[1], bh[2], bh[3], sKhi + boff);
                mma16816(sacc[2*nb],   ah[0], ah[1], ah[2], ah[3], bh[0], bh[1]);
                mma16816(sacc[2*nb+1], ah[0], ah[1], ah[2], ah[3], bh[2], bh[3]);
                mma16816(sacc[2*nb],   al[0], al[1], al[2], al[3], bh[0], bh[1]);
                mma16816(sacc[2*nb+1], al[0], al[1], al[2], al[3], bh[2], bh[3]);
                ldm_x4(bh[0], bh[1], bh[2], bh[3], sKlo + boff);
                mma16816(sacc[2*nb],   ah[0], ah[1], ah[2], ah[3], bh[0], bh[1]);
                mma16816(sacc[2*nb+1], ah[0], ah[1], ah[2], ah[3], bh[2], bh[3]);
            }
        }

        // ---- causal mask on diagonal tile (rows 16*wid+g, +8) ----
        if (j == qt) {
            const int r0 = 16 * wid + g;
#pragma unroll
            for (int nt = 0; nt < 16; nt++) {
                const int c0 = nt * 8 + t * 2;
                if (c0     > r0)     sacc[nt][0] = 0.0f;
                if (c0 + 1 > r0)     sacc[nt][1] = 0.0f;
                if (c0     > r0 + 8) sacc[nt][2] = 0.0f;
                if (c0 + 1 > r0 + 8) sacc[nt][3] = 0.0f;
            }
        }

        __syncthreads();            // all warps done reading K(j)
        if (j + 1 < j1) {
            const size_t kt = (size_t)(b * 16 + j + 1) * TILE_ELE;
            cpa_tile(sKhi, g_k_hi + kt, tid);
            cpa_tile(sKlo, g_k_lo + kt, tid);
        }
        CP_COMMIT();                 // group: K(j+1) (possibly empty)
        CP_WAIT(1);                  // V(j) complete (K(j+1) may pend)
        __syncthreads();             // V visible

        // ================= GEMM2: O += S V (A from registers) ===============
#pragma unroll
        for (int ks = 0; ks < 8; ks++) {
            // Build S A-fragments (hi & lo) for k-cols [16ks,16ks+16)
            uint32_t sh[4], sl[4];
            split2(sacc[2*ks][0],   sacc[2*ks][1],   sh[0], sl[0]);
            split2(sacc[2*ks][2],   sacc[2*ks][3],   sh[1], sl[1]);
            split2(sacc[2*ks+1][0], sacc[2*ks+1][1], sh[2], sl[2]);
            split2(sacc[2*ks+1][2], sacc[2*ks+1][3], sh[3], sl[3]);
            const uint32_t kso = (uint32_t)(ks * 16) * 2;
#pragma unroll
            for (int hb = 0; hb < 8; hb++) {
                const uint32_t boff = b_lane + (uint32_t)(hb * 16 * KPAD) * 2 + kso;
                uint32_t bh[4];
                ldm_x4(bh[0], bh[1], bh[2], bh[3], sVhi + boff);
                mma16816(oacc[2*hb],   sh[0], sh[1], sh[2], sh[3], bh[0], bh[1]);
                mma16816(oacc[2*hb+1], sh[0], sh[1], sh[2], sh[3], bh[2], bh[3]);
                mma16816(oacc[2*hb],   sl[0], sl[1], sl[2], sl[3], bh[0], bh[1]);
                mma16816(oacc[2*hb+1], sl[0], sl[1], sl[2], sl[3], bh[2], bh[3]);
                ldm_x4(bh[0], bh[1], bh[2], bh[3], sVlo + boff);
                mma16816(oacc[2*hb],   sh[0], sh[1], sh[2], sh[3], bh[0], bh[1]);
                mma16816(oacc[2*hb+1], sh[0], sh[1], sh[2], sh[3], bh[2], bh[3]);
            }
        }

        __syncthreads();            // all warps done reading V(j)
        if (j + 1 < j1) {
            const size_t kt = (size_t)(b * 16 + j + 1) * TILE_ELE;
            cpa_tile(sVhi, g_v_hi + kt, tid);
            cpa_tile(sVlo, g_v_lo + kt, tid);
        }
        CP_COMMIT();                 // group: V(j+1) (possibly empty)
        CP_WAIT(1);                  // K(j+1) complete (V(j+1) may pend)
        __syncthreads();             // K visible
    }

    // ---- epilogue: rows 16*wid+g (+8), cols ht*8 + 2t ----
    const int r0 = 16 * wid + g;
    if (!partial) {
        const size_t rowbase = (size_t)b * SEQ + (size_t)qt * 128;
#pragma unroll
        for (int ht = 0; ht < 16; ht++) {
            int c = ht * 8 + t * 2;
            *(float2*)&out[(rowbase + r0) * HEAD + c]     = make_float2(oacc[ht][0], oacc[ht][1]);
            *(float2*)&out[(rowbase + r0 + 8) * HEAD + c] = make_float2(oacc[ht][2], oacc[ht][3]);
        }
    } else {
        float* dst = g_opart + (size_t)(b * 8 + (qt - 8)) * TILE_ELE;
#pragma unroll
        for (int ht = 0; ht < 16; ht++) {
            int c = ht * 8 + t * 2;
            *(float2*)&dst[(size_t)r0 * HEAD + c]       = make_float2(oacc[ht][0], oacc[ht][1]);
            *(float2*)&dst[(size_t)(r0 + 8) * HEAD + c] = make_float2(oacc[ht][2], oacc[ht][3]);
        }
    }
}

// ---------------------------------------------------------------------------
// Kernel 3: add partial O chunks into out (qt >= 8 only).
// ---------------------------------------------------------------------------
__global__ __launch_bounds__(256) void reduce_partials(float* __restrict__ out)
{
    int gid = blockIdx.x * 256 + threadIdx.x;
    int tile = gid >> 12;
    int w = gid & 4095;
    int b = tile >> 3, qti = tile & 7;
    float4* o = (float4*)(out + ((size_t)b * SEQ + (size_t)(qti + 8) * 128) * HEAD) + w;
    const float4* p = (const float4*)(g_opart + (size_t)tile * TILE_ELE) + w;
    float4 ov = *o, pv = *p;
    ov.x += pv.x; ov.y += pv.y; ov.z += pv.z; ov.w += pv.w;
    *o = ov;
}

// ---------------------------------------------------------------------------
// Launch
// ---------------------------------------------------------------------------
extern "C" void kernel_launch(void* const* d_in, const int* in_sizes, int n_in,
                              void* d_out, int out_size)
{
    const float* key   = (const float*)d_in[0];
    const float* query = (const float*)d_in[1];
    const float* value = (const float*)d_in[2];
    const float* w_q   = (const float*)d_in[3];
    const float* w_k   = (const float*)d_in[4];
    const float* w_v   = (const float*)d_in[5];
    float* out = (float*)d_out;

    prep_w<<<768, 256>>>(w_q, w_k, w_v);

    cudaFuncSetAttribute(proj_tc,
                         cudaFuncAttributeMaxDynamicSharedMemorySize, PSM_TOTAL);
    dim3 g1(NTILES, 3);
    proj_tc<<<g1, 256, PSM_TOTAL>>>(key, query, value);

    cudaFuncSetAttribute(retention_tc,
                         cudaFuncAttributeMaxDynamicSharedMemorySize, SMR_BYTES);
    dim3 g2(BATCH, 24);
    retention_tc<<<g2, 256, SMR_BYTES>>>(out);

    reduce_partials<<<1024, 256>>>(out);
}

// round 6
// speedup vs baseline: 4.2726x; 1.0543x over previous
#include <cuda_runtime.h>
#include <cuda_bf16.h>
#include <cstdint>

// Problem dims
#define BATCH 8
#define SEQ   2048
#define EMB   1024
#define HEAD  128
#define MROWS (BATCH * SEQ)     // 16384
#define NTILES (MROWS / 128)    // 128
#define TILE_ELE (128 * 128)

// Pre-split bf16 projected tensors, row-major per 128x128 tile.
// Q tiles: [m][h];  K tiles: [n][h];  V tiles: TRANSPOSED [h][n].
__device__ __nv_bfloat16 g_q_hi[NTILES * TILE_ELE];
__device__ __nv_bfloat16 g_q_lo[NTILES * TILE_ELE];
__device__ __nv_bfloat16 g_k_hi[NTILES * TILE_ELE];
__device__ __nv_bfloat16 g_k_lo[NTILES * TILE_ELE];
__device__ __nv_bfloat16 g_v_hi[NTILES * TILE_ELE];
__device__ __nv_bfloat16 g_v_lo[NTILES * TILE_ELE];

// Pre-split weights: [w][n][k], k contiguous
__device__ __nv_bfloat16 g_w_hi[3 * 128 * 1024];
__device__ __nv_bfloat16 g_w_lo[3 * 128 * 1024];

// Partial O accumulators for split-K chunks (qt >= 8)
__device__ float g_opart[BATCH * 8 * TILE_ELE];

// Chunk schedule: 24 chunks per batch, longest first.
__constant__ int c_qt[24] = {15,15,14, 7,14,13,13,12, 6,12,11,11,10, 5,10, 9, 9, 8, 4, 8, 3, 2, 1, 0};
__constant__ int c_j0[24] = { 0, 8, 0, 0, 8, 0, 7, 0, 0, 7, 0, 6, 0, 0, 6, 0, 5, 0, 0, 5, 0, 0, 0, 0};
__constant__ int c_j1[24] = { 8,16, 8, 8,15, 7,14, 7, 7,13, 6,12, 6, 6,11, 5,10, 5, 5, 9, 4, 3, 2, 1};

// ---------------------------------------------------------------------------
// PTX helpers (family-generic)
// ---------------------------------------------------------------------------
__device__ __forceinline__ uint32_t smem_u32(const void* p) {
    uint32_t a;
    asm("{ .reg .u64 t; cvta.to.shared.u64 t, %1; cvt.u32.u64 %0, t; }"
        : "=r"(a) : "l"(p));
    return a;
}

__device__ __forceinline__ void mma16816(float* c,
    uint32_t a0, uint32_t a1, uint32_t a2, uint32_t a3,
    uint32_t b0, uint32_t b1)
{
    asm volatile(
        "mma.sync.aligned.m16n8k16.row.col.f32.bf16.bf16.f32 "
        "{%0,%1,%2,%3}, {%4,%5,%6,%7}, {%8,%9}, {%0,%1,%2,%3};"
        : "+f"(c[0]), "+f"(c[1]), "+f"(c[2]), "+f"(c[3])
        : "r"(a0), "r"(a1), "r"(a2), "r"(a3), "r"(b0), "r"(b1));
}

__device__ __forceinline__ void ldm_x4(uint32_t& r0, uint32_t& r1,
                                       uint32_t& r2, uint32_t& r3, uint32_t addr)
{
    asm volatile("ldmatrix.sync.aligned.m8n8.x4.shared.b16 {%0,%1,%2,%3}, [%4];"
                 : "=r"(r0), "=r"(r1), "=r"(r2), "=r"(r3) : "r"(addr));
}

#define CP_ASYNC16(dst, src) \
    asm volatile("cp.async.cg.shared.global [%0], [%1], 16;" :: "r"(dst), "l"(src))
#define CP_COMMIT() asm volatile("cp.async.commit_group;" ::: "memory")
#define CP_WAIT(n)  asm volatile("cp.async.wait_group %0;" :: "n"(n) : "memory")

__device__ __forceinline__ void split2(float a0, float a1, uint32_t& hi, uint32_t& lo) {
    __nv_bfloat162 h = __float22bfloat162_rn(make_float2(a0, a1));
    float2 hf = __bfloat1622float2(h);
    __nv_bfloat162 l = __float22bfloat162_rn(make_float2(a0 - hf.x, a1 - hf.y));
    hi = *reinterpret_cast<uint32_t*>(&h);
    lo = *reinterpret_cast<uint32_t*>(&l);
}

// ---------------------------------------------------------------------------
// Kernel 0: pre-split W into bf16 hi/lo, layout [w][n][k]
// ---------------------------------------------------------------------------
__global__ __launch_bounds__(256) void prep_w(
    const float* __restrict__ wq, const float* __restrict__ wk,
    const float* __restrict__ wv)
{
    int u = blockIdx.x * 256 + threadIdx.x;
    int w = u >> 16;
    int rem = u & 65535;
    int n = rem >> 9;
    int kp = (rem & 511) * 2;
    const float* W = (w == 0) ? wq : (w == 1) ? wk : wv;
    float w0 = W[(size_t)kp * HEAD + n];
    float w1 = W[(size_t)(kp + 1) * HEAD + n];
    uint32_t hi, lo;
    split2(w0, w1, hi, lo);
    size_t off = ((size_t)w * 128 + n) * 1024 + kp;
    *(uint32_t*)&g_w_hi[off] = hi;
    *(uint32_t*)&g_w_lo[off] = lo;
}

// ---------------------------------------------------------------------------
// Kernel 1: projection GEMM  C[M,128] = A[M,1024] @ W[1024,128]
// Fully pipelined: A double-buffered (convert overlaps MMA), W double-buffered
// cp.async, ONE barrier per k-block, fused 3-product warp GEMM.
// ---------------------------------------------------------------------------
#define PKPAD 72
#define PABUF (128 * PKPAD * 2)     // 18432 B per bf16 buffer
// smem stages (bytes): Ahi0 0, Alo0 1, Ahi1 2, Alo1 3, Whi0 4, Wlo0 5, Whi1 6, Wlo1 7
#define PSM_TOTAL (8 * PABUF)       // 147456

// Fused 3-product warp GEMM for one 128x64 A block x 64(K)x32 W slab.
__device__ __forceinline__ void warp_gemm_proj(float acc[4][4][4],
    uint32_t sAhi, uint32_t sAlo, uint32_t sWhi, uint32_t sWlo,
    uint32_t a_lane, uint32_t b_lane)
{
#pragma unroll
    for (int ks = 0; ks < 4; ks++) {
        const uint32_t kso = (uint32_t)(ks * 16) * 2;
        uint32_t ah[4][4], al[4][4];
#pragma unroll
        for (int mt = 0; mt < 4; mt++) {
            const uint32_t ao = a_lane + (uint32_t)(mt * 16 * PKPAD) * 2 + kso;
            ldm_x4(ah[mt][0], ah[mt][1], ah[mt][2], ah[mt][3], sAhi + ao);
            ldm_x4(al[mt][0], al[mt][1], al[mt][2], al[mt][3], sAlo + ao);
        }
#pragma unroll
        for (int np = 0; np < 2; np++) {
            const uint32_t bo = b_lane + (uint32_t)(np * 16 * PKPAD) * 2 + kso;
            uint32_t bh[4], bl[4];
            ldm_x4(bh[0], bh[1], bh[2], bh[3], sWhi + bo);
            ldm_x4(bl[0], bl[1], bl[2], bl[3], sWlo + bo);
#pragma unroll
            for (int mt = 0; mt < 4; mt++) {
                mma16816(acc[mt][2*np],   ah[mt][0], ah[mt][1], ah[mt][2], ah[mt][3], bh[0], bh[1]);
                mma16816(acc[mt][2*np+1], ah[mt][0], ah[mt][1], ah[mt][2], ah[mt][3], bh[2], bh[3]);
                mma16816(acc[mt][2*np],   ah[mt][0], ah[mt][1], ah[mt][2], ah[mt][3], bl[0], bl[1]);
                mma16816(acc[mt][2*np+1], ah[mt][0], ah[mt][1], ah[mt][2], ah[mt][3], bl[2], bl[3]);
                mma16816(acc[mt][2*np],   al[mt][0], al[mt][1], al[mt][2], al[mt][3], bh[0], bh[1]);
                mma16816(acc[mt][2*np+1], al[mt][0], al[mt][1], al[mt][2], al[mt][3], bh[2], bh[3]);
            }
        }
    }
}

__global__ __launch_bounds__(256) void proj_tc(
    const float* __restrict__ in_key,
    const float* __restrict__ in_query,
    const float* __restrict__ in_value)
{
    extern __shared__ __align__(16) char psm[];
    const uint32_t sb = smem_u32(psm);

    const float* A;
    const int p = blockIdx.y;
    if (p == 0)      A = in_query;
    else if (p == 1) A = in_key;
    else             A = in_value;

    const int tid  = threadIdx.x;
    const int wid  = tid >> 5, lane = tid & 31;
    const int g    = lane >> 2, t = lane & 3;
    const int mbase = (wid & 1) * 64;
    const int nbase = (wid >> 1) * 32;
    const int tile = blockIdx.x;
    const int rowBase = tile * 128;

    const uint32_t a_lane = ((mbase + (lane & 15)) * PKPAD + (lane >> 4) * 8) * 2;
    const uint32_t b_lane = ((nbase + (lane & 7) + ((lane >> 4) << 3)) * PKPAD
                             + ((lane >> 3) & 1) * 8) * 2;

    const int aRow0 = tid >> 4;          // 0..15, rows +16 apart
    const int aC4   = (tid & 15) * 4;    // col within 64-wide block

    float acc[4][4][4];
#pragma unroll
    for (int i = 0; i < 4; i++)
#pragma unroll
        for (int j = 0; j < 4; j++)
#pragma unroll
            for (int q = 0; q < 4; q++) acc[i][j][q] = 0.0f;

    const __nv_bfloat16* wsrc_hi = g_w_hi + (size_t)p * 128 * 1024;
    const __nv_bfloat16* wsrc_lo = g_w_lo + (size_t)p * 128 * 1024;

    auto cpa_w = [&](int kb, int s) {
        uint32_t dhi = sb + (4 + 2 * s) * PABUF;
        uint32_t dlo = dhi + PABUF;
#pragma unroll
        for (int it = 0; it < 4; it++) {
            int u = tid + it * 256;
            int row = u >> 3, c = u & 7;
            uint32_t doff = (uint32_t)(row * PKPAD + c * 8) * 2;
            size_t soff = (size_t)row * 1024 + kb * 64 + c * 8;
            CP_ASYNC16(dhi + doff, (const char*)(wsrc_hi + soff));
            CP_ASYNC16(dlo + doff, (const char*)(wsrc_lo + soff));
        }
        CP_COMMIT();
    };

    auto conv_a = [&](const float4* areg, int s) {
        const uint32_t dhi = sb + 2 * s * PABUF;
        const uint32_t dlo = dhi + PABUF;
#pragma unroll
        for (int it = 0; it < 8; it++) {
            uint32_t h0, l0, h1, l1;
            split2(areg[it].x, areg[it].y, h0, l0);
            split2(areg[it].z, areg[it].w, h1, l1);
            uint32_t doff = (uint32_t)((aRow0 + it * 16) * PKPAD + aC4) * 2;
            asm volatile("st.shared.v2.b32 [%0], {%1,%2};" :: "r"(dhi + doff), "r"(h0), "r"(h1));
            asm volatile("st.shared.v2.b32 [%0], {%1,%2};" :: "r"(dlo + doff), "r"(l0), "r"(l1));
        }
    };

    // Prologue: A(0) -> regs -> stage 0 STS; A(1) -> regs; W(0) cp.async.
    float4 areg[8];
#pragma unroll
    for (int it = 0; it < 8; it++)
        areg[it] = *(const float4*)&A[(size_t)(rowBase + aRow0 + it * 16) * EMB + aC4];
    conv_a(areg, 0);
#pragma unroll
    for (int it = 0; it < 8; it++)
        areg[it] = *(const float4*)&A[(size_t)(rowBase + aRow0 + it * 16) * EMB + 64 + aC4];
    cpa_w(0, 0);

    for (int kb = 0; kb < 16; kb++) {
        CP_WAIT(0);            // W(kb) arrived (it is the only outstanding group)
        __syncthreads();       // all warps: MMA(kb-1) done; A(kb) STS + W(kb) visible

        if (kb < 15) {
            cpa_w(kb + 1, (kb + 1) & 1);     // stage free: MMA(kb-1) was its last reader
            conv_a(areg, (kb + 1) & 1);      // A(kb+1) regs -> other stage
        }
        if (kb < 14) {
            const int k0n = (kb + 2) * 64;
#pragma unroll
            for (int it = 0; it < 8; it++)
                areg[it] = *(const float4*)&A[(size_t)(rowBase + aRow0 + it * 16) * EMB + k0n + aC4];
        }

        const uint32_t sAhi = sb + 2 * (kb & 1) * PABUF;
        const uint32_t sWhi = sb + (4 + 2 * (kb & 1)) * PABUF;
        warp_gemm_proj(acc, sAhi, sAhi + PABUF, sWhi, sWhi + PABUF, a_lane, b_lane);
    }

    // Epilogue: split to bf16 hi/lo, store tiles.
    __nv_bfloat16 *dhi, *dlo;
    if (p == 0)      { dhi = g_q_hi; dlo = g_q_lo; }
    else if (p == 1) { dhi = g_k_hi; dlo = g_k_lo; }
    else             { dhi = g_v_hi; dlo = g_v_lo; }
    const size_t base = (size_t)tile * TILE_ELE;

    if (p != 2) {
#pragma unroll
        for (int mt = 0; mt < 4; mt++)
#pragma unroll
            for (int nt = 0; nt < 4; nt++) {
                int r0 = mbase + mt * 16 + g;
                int c  = nbase + nt * 8 + t * 2;
                uint32_t hi, lo;
                split2(acc[mt][nt][0], acc[mt][nt][1], hi, lo);
                *(uint32_t*)(dhi + base + (size_t)r0 * 128 + c) = hi;
                *(uint32_t*)(dlo + base + (size_t)r0 * 128 + c) = lo;
                split2(acc[mt][nt][2], acc[mt][nt][3], hi, lo);
                *(uint32_t*)(dhi + base + (size_t)(r0 + 8) * 128 + c) = hi;
                *(uint32_t*)(dlo + base + (size_t)(r0 + 8) * 128 + c) = lo;
            }
    } else {
#pragma unroll
        for (int mt = 0; mt < 4; mt++)
#pragma unroll
            for (int nt = 0; nt < 4; nt++)
#pragma unroll
                for (int q = 0; q < 4; q++) {
                    int row = mbase + mt * 16 + g + (q >> 1) * 8;
                    int col = nbase + nt * 8 + t * 2 + (q & 1);
                    float v = acc[mt][nt][q];
                    __nv_bfloat16 h = __float2bfloat16(v);
                    __nv_bfloat16 l = __float2bfloat16(v - __bfloat162float(h));
                    dhi[base + (size_t)col * 128 + row] = h;
                    dlo[base + (size_t)col * 128 + row] = l;
                }
    }
}

// ---------------------------------------------------------------------------
// Kernel 2: fused causal retention (unchanged from round 5).
// ---------------------------------------------------------------------------
#define KPAD 136
#define RB (128 * KPAD * 2)
#define SMR_BYTES (6 * RB)

__device__ __forceinline__ void cpa_tile(uint32_t dst, const __nv_bfloat16* __restrict__ src,
                                         int tid) {
#pragma unroll
    for (int it = 0; it < 8; it++) {
        int u = tid + it * 256;
        int row = u >> 4, c = u & 15;
        CP_ASYNC16(dst + (uint32_t)(row * KPAD + c * 8) * 2, (const char*)src + (size_t)u * 16);
    }
}

__global__ __launch_bounds__(256) void retention_tc(float* __restrict__ out)
{
    extern __shared__ __align__(16) char smraw[];
    const uint32_t sb = smem_u32(smraw);
    const uint32_t sQhi = sb,         sQlo = sb + RB;
    const uint32_t sKhi = sb + 2*RB,  sKlo = sb + 3*RB;
    const uint32_t sVhi = sb + 4*RB,  sVlo = sb + 5*RB;

    const int tid  = threadIdx.x;
    const int wid  = tid >> 5, lane = tid & 31;
    const int g    = lane >> 2, t = lane & 3;

    const int b   = blockIdx.x;
    const int cid = blockIdx.y;
    const int qt  = c_qt[cid];
    const int j0  = c_j0[cid];
    const int j1  = c_j1[cid];
    const bool partial = (j1 != qt + 1);
    const int qtile = b * 16 + qt;

    const uint32_t a_lane = (uint32_t)((16 * wid + (lane & 15)) * KPAD + (lane >> 4) * 8) * 2;
    const uint32_t b_lane = (uint32_t)(((lane & 7) + ((lane >> 4) << 3)) * KPAD
                                       + ((lane >> 3) & 1) * 8) * 2;

    cpa_tile(sQhi, g_q_hi + (size_t)qtile * TILE_ELE, tid);
    cpa_tile(sQlo, g_q_lo + (size_t)qtile * TILE_ELE, tid);
    CP_COMMIT();
    {
        const size_t kt = (size_t)(b * 16 + j0) * TILE_ELE;
        cpa_tile(sKhi, g_k_hi + kt, tid);
        cpa_tile(sKlo, g_k_lo + kt, tid);
        CP_COMMIT();
        cpa_tile(sVhi, g_v_hi + kt, tid);
        cpa_tile(sVlo, g_v_lo + kt, tid);
        CP_COMMIT();
    }
    CP_WAIT(1);
    __syncthreads();

    float oacc[16][4];
#pragma unroll
    for (int i = 0; i < 16; i++)
#pragma unroll
        for (int q = 0; q < 4; q++) oacc[i][q] = 0.0f;

    for (int j = j0; j < j1; j++) {
        float sacc[16][4];
#pragma unroll
        for (int i = 0; i < 16; i++)
#pragma unroll
            for (int q = 0; q < 4; q++) sacc[i][q] = 0.0f;

#pragma unroll 2
        for (int ks = 0; ks < 8; ks++) {
            const uint32_t kso = (uint32_t)(ks * 16) * 2;
            uint32_t ah[4], al[4];
            ldm_x4(ah[0], ah[1], ah[2], ah[3], sQhi + a_lane + kso);
            ldm_x4(al[0], al[1], al[2], al[3], sQlo + a_lane + kso);
#pragma unroll
            for (int nb = 0; nb < 8; nb++) {
                const uint32_t boff = b_lane + (uint32_t)(nb * 16 * KPAD) * 2 + kso;
                uint32_t bh[4];
                ldm_x4(bh[0], bh[1], bh[2], bh[3], sKhi + boff);
                mma16816(sacc[2*nb],   ah[0], ah[1], ah[2], ah[3], bh[0], bh[1]);
                mma16816(sacc[2*nb+1], ah[0], ah[1], ah[2], ah[3], bh[2], bh[3]);
                mma16816(sacc[2*nb],   al[0], al[1], al[2], al[3], bh[0], bh[1]);
                mma16816(sacc[2*nb+1], al[0], al[1], al[2], al[3], bh[2], bh[3]);
                ldm_x4(bh[0], bh[1], bh[2], bh[3], sKlo + boff);
                mma16816(sacc[2*nb],   ah[0], ah[1], ah[2], ah[3], bh[0], bh[1]);
                mma16816(sacc[2*nb+1], ah[0], ah[1], ah[2], ah[3], bh[2], bh[3]);
            }
        }

        if (j == qt) {
            const int r0 = 16 * wid + g;
#pragma unroll
            for (int nt = 0; nt < 16; nt++) {
                const int c0 = nt * 8 + t * 2;
                if (c0     > r0)     sacc[nt][0] = 0.0f;
                if (c0 + 1 > r0)     sacc[nt][1] = 0.0f;
                if (c0     > r0 + 8) sacc[nt][2] = 0.0f;
                if (c0 + 1 > r0 + 8) sacc[nt][3] = 0.0f;
            }
        }

        __syncthreads();
        if (j + 1 < j1) {
            const size_t kt = (size_t)(b * 16 + j + 1) * TILE_ELE;
            cpa_tile(sKhi, g_k_hi + kt, tid);
            cpa_tile(sKlo, g_k_lo + kt, tid);
        }
        CP_COMMIT();
        CP_WAIT(1);
        __syncthreads();

#pragma unroll
        for (int ks = 0; ks < 8; ks++) {
            uint32_t sh[4], sl[4];
            split2(sacc[2*ks][0],   sacc[2*ks][1],   sh[0], sl[0]);
            split2(sacc[2*ks][2],   sacc[2*ks][3],   sh[1], sl[1]);
            split2(sacc[2*ks+1][0], sacc[2*ks+1][1], sh[2], sl[2]);
            split2(sacc[2*ks+1][2], sacc[2*ks+1][3], sh[3], sl[3]);
            const uint32_t kso = (uint32_t)(ks * 16) * 2;
#pragma unroll
            for (int hb = 0; hb < 8; hb++) {
                const uint32_t boff = b_lane + (uint32_t)(hb * 16 * KPAD) * 2 + kso;
                uint32_t bh[4];
                ldm_x4(bh[0], bh[1], bh[2], bh[3], sVhi + boff);
                mma16816(oacc[2*hb],   sh[0], sh[1], sh[2], sh[3], bh[0], bh[1]);
                mma16816(oacc[2*hb+1], sh[0], sh[1], sh[2], sh[3], bh[2], bh[3]);
                mma16816(oacc[2*hb],   sl[0], sl[1], sl[2], sl[3], bh[0], bh[1]);
                mma16816(oacc[2*hb+1], sl[0], sl[1], sl[2], sl[3], bh[2], bh[3]);
                ldm_x4(bh[0], bh[1], bh[2], bh[3], sVlo + boff);
                mma16816(oacc[2*hb],   sh[0], sh[1], sh[2], sh[3], bh[0], bh[1]);
                mma16816(oacc[2*hb+1], sh[0], sh[1], sh[2], sh[3], bh[2], bh[3]);
            }
        }

        __syncthreads();
        if (j + 1 < j1) {
            const size_t kt = (size_t)(b * 16 + j + 1) * TILE_ELE;
            cpa_tile(sVhi, g_v_hi + kt, tid);
            cpa_tile(sVlo, g_v_lo + kt, tid);
        }
        CP_COMMIT();
        CP_WAIT(1);
        __syncthreads();
    }

    const int r0 = 16 * wid + g;
    if (!partial) {
        const size_t rowbase = (size_t)b * SEQ + (size_t)qt * 128;
#pragma unroll
        for (int ht = 0; ht < 16; ht++) {
            int c = ht * 8 + t * 2;
            *(float2*)&out[(rowbase + r0) * HEAD + c]     = make_float2(oacc[ht][0], oacc[ht][1]);
            *(float2*)&out[(rowbase + r0 + 8) * HEAD + c] = make_float2(oacc[ht][2], oacc[ht][3]);
        }
    } else {
        float* dst = g_opart + (size_t)(b * 8 + (qt - 8)) * TILE_ELE;
#pragma unroll
        for (int ht = 0; ht < 16; ht++) {
            int c = ht * 8 + t * 2;
            *(float2*)&dst[(size_t)r0 * HEAD + c]       = make_float2(oacc[ht][0], oacc[ht][1]);
            *(float2*)&dst[(size_t)(r0 + 8) * HEAD + c] = make_float2(oacc[ht][2], oacc[ht][3]);
        }
    }
}

// ---------------------------------------------------------------------------
// Kernel 3: add partial O chunks into out (qt >= 8 only).
// ---------------------------------------------------------------------------
__global__ __launch_bounds__(256) void reduce_partials(float* __restrict__ out)
{
    int gid = blockIdx.x * 256 + threadIdx.x;
    int tile = gid >> 12;
    int w = gid & 4095;
    int b = tile >> 3, qti = tile & 7;
    float4* o = (float4*)(out + ((size_t)b * SEQ + (size_t)(qti + 8) * 128) * HEAD) + w;
    const float4* p = (const float4*)(g_opart + (size_t)tile * TILE_ELE) + w;
    float4 ov = *o, pv = *p;
    ov.x += pv.x; ov.y += pv.y; ov.z += pv.z; ov.w += pv.w;
    *o = ov;
}

// ---------------------------------------------------------------------------
// Launch
// ---------------------------------------------------------------------------
extern "C" void kernel_launch(void* const* d_in, const int* in_sizes, int n_in,
                              void* d_out, int out_size)
{
    const float* key   = (const float*)d_in[0];
    const float* query = (const float*)d_in[1];
    const float* value = (const float*)d_in[2];
    const float* w_q   = (const float*)d_in[3];
    const float* w_k   = (const float*)d_in[4];
    const float* w_v   = (const float*)d_in[5];
    float* out = (float*)d_out;

    prep_w<<<768, 256>>>(w_q, w_k, w_v);

    cudaFuncSetAttribute(proj_tc,
                         cudaFuncAttributeMaxDynamicSharedMemorySize, PSM_TOTAL);
    dim3 g1(NTILES, 3);
    proj_tc<<<g1, 256, PSM_TOTAL>>>(key, query, value);

    cudaFuncSetAttribute(retention_tc,
                         cudaFuncAttributeMaxDynamicSharedMemorySize, SMR_BYTES);
    dim3 g2(BATCH, 24);
    retention_tc<<<g2, 256, SMR_BYTES>>>(out);

    reduce_partials<<<1024, 256>>>(out);
}